// round 12
// baseline (speedup 1.0000x reference)
#include <cuda_runtime.h>
#include <cuda_bf16.h>
#include <math.h>

#define BB 16
#define CC 128
#define NBCODE 16384
#define NTOT 5456
#define FHN (BB*CC*16*16)   // 524288
#define NCHUNK 128          // 128 codes per chunk
#define CO_SMEM ((256*68 + 128*68)*4)               // 104448 bytes
#define CONV_SMEM ((2*256*67 + 2*16*577)*4)         // 211072 bytes

// ---- device scratch (no allocations allowed) ----
__device__ float g_frest[FHN];
__device__ float g_rnc[4096*CC];
__device__ float g_hs[FHN];
__device__ float g_chmin[4096*NCHUNK];
__device__ unsigned long long g_best[4096];
__device__ int g_idx[4096];
__device__ int g_counts[NBCODE];
__device__ float g_loss;
__device__ float g_esq[NBCODE];
__device__ int g_esqmax = 0;                  // monotone; no per-call reset needed
__device__ unsigned g_embw[NBCODE*64];        // bf16x2 words [code][64]
__device__ float g_embT[CC*NBCODE];           // transposed fp32 codebook [d][code]

// ------------------------------------------------------------------
__device__ __forceinline__ void mma16816(float* d, const unsigned* a, unsigned b0, unsigned b1) {
    asm volatile("mma.sync.aligned.m16n8k16.row.col.f32.bf16.bf16.f32 "
                 "{%0,%1,%2,%3}, {%4,%5,%6,%7}, {%8,%9}, {%0,%1,%2,%3};"
                 : "+f"(d[0]), "+f"(d[1]), "+f"(d[2]), "+f"(d[3])
                 : "r"(a[0]), "r"(a[1]), "r"(a[2]), "r"(a[3]), "r"(b0), "r"(b1));
}
__device__ __forceinline__ unsigned fkey(float f) {
    unsigned u = __float_as_uint(f);
    return (u & 0x80000000u) ? ~u : (u | 0x80000000u);
}
__device__ __forceinline__ unsigned pack2(float a, float b) {
    __nv_bfloat162 t = __floats2bfloat162_rn(a, b);
    return *(unsigned*)&t;
}

// ------------------------------------------------------------------
// Fused one-time prep: [0,2048) init, [2048,2112) esq, [2112,6208) pack,
// [6208,8256) 32x32 transpose tiles.
__global__ void prep_all(const float* __restrict__ f, float* __restrict__ fhat,
                         const float* __restrict__ emb) {
    __shared__ float t[32][33];
    int blk = blockIdx.x, tid = threadIdx.x;
    if (blk < 2048) {
        int i = blk * 256 + tid;
        fhat[i] = 0.0f;
        g_frest[i] = f[i];
        if (i < NBCODE) g_counts[i] = 0;
        if (i == 0) g_loss = 0.0f;
    } else if (blk < 2112) {
        int k = (blk - 2048) * 256 + tid;
        const float* e = emb + (size_t)k * CC;
        float s = 0.0f;
#pragma unroll 8
        for (int d = 0; d < CC; d++) s = fmaf(e[d], e[d], s);
        g_esq[k] = s;
        atomicMax(&g_esqmax, __float_as_int(s));   // s>=0: int order == float order
    } else if (blk < 6208) {
        int i = (blk - 2112) * 256 + tid;          // NBCODE*64 words
        float2 v = ((const float2*)emb)[i];
        g_embw[i] = pack2(v.x, v.y);
    } else {
        int idx = blk - 6208;                      // 2048 tiles
        int k0 = (idx & 511) * 32, d0 = (idx >> 9) * 32;
        int x = tid & 31, y0 = tid >> 5;
        for (int yy = y0; yy < 32; yy += 8)
            t[yy][x] = emb[(size_t)(k0 + yy) * CC + d0 + x];
        __syncthreads();
        for (int yy = y0; yy < 32; yy += 8)
            g_embT[(size_t)(d0 + yy) * NBCODE + k0 + x] = t[x][yy];
    }
}

// thread-per-output pooling (fct = 2,4)
__global__ void pool_kernel(int sn, int fct) {
    int i = blockIdx.x * blockDim.x + threadIdx.x;
    int N = BB * sn * sn;
    if (i >= N * CC) return;
    int n = i / CC, c = i % CC;
    int t = n % sn;
    int s = (n / sn) % sn;
    int b = n / (sn * sn);
    const float* base = g_frest + ((size_t)(b * CC + c)) * 256;
    float acc = 0.0f;
    for (int dj = 0; dj < fct; dj++)
        for (int dl = 0; dl < fct; dl++)
            acc += base[(s * fct + dj) * 16 + (t * fct + dl)];
    g_rnc[n * CC + c] = acc * (1.0f / (float)(fct * fct));
}

// warp-per-output pooling, fct=16 (sn=1)
__global__ void pool16_kernel() {
    int out = blockIdx.x * 8 + (threadIdx.x >> 5);
    int lane = threadIdx.x & 31;
    const float4* base = (const float4*)(g_frest + (size_t)out * 256);
    float4 v1 = base[lane], v2 = base[lane + 32];
    float s = v1.x + v1.y + v1.z + v1.w + v2.x + v2.y + v2.z + v2.w;
#pragma unroll
    for (int o = 16; o > 0; o >>= 1) s += __shfl_xor_sync(0xFFFFFFFFu, s, o);
    if (lane == 0) g_rnc[out] = s * (1.0f / 256.0f);
}

// warp-per-output pooling, fct=8 (sn=2)
__global__ void pool8_kernel() {
    int out = blockIdx.x * 8 + (threadIdx.x >> 5);
    int lane = threadIdx.x & 31;
    int n = out >> 7, c = out & 127;
    int t = n & 1, s = (n >> 1) & 1, b = n >> 2;
    const float* base = g_frest + ((size_t)(b * CC + c)) * 256;
    int dj = lane >> 2, dl = (lane & 3) * 2;
    const float2* p = (const float2*)(base + (s * 8 + dj) * 16 + t * 8 + dl);
    float2 v = *p;
    float sm = v.x + v.y;
#pragma unroll
    for (int o = 16; o > 0; o >>= 1) sm += __shfl_xor_sync(0xFFFFFFFFu, sm, o);
    if (lane == 0) g_rnc[out] = sm * (1.0f / 64.0f);
}

// sn=16 "pool" = identity transpose, coalesced both ways via 32x32 tiles
__global__ void pool1_kernel() {
    __shared__ float t[32][33];
    int b  = blockIdx.x >> 5;
    int ct = (blockIdx.x >> 3) & 3;
    int pt = blockIdx.x & 7;
    int x = threadIdx.x & 31, y0 = threadIdx.x >> 5;
    const float* src = g_frest + ((size_t)(b * CC + ct * 32)) * 256 + pt * 32;
    for (int yy = y0; yy < 32; yy += 8)
        t[yy][x] = src[(size_t)yy * 256 + x];
    __syncthreads();
    float* dst = g_rnc + ((size_t)(b * 256 + pt * 32)) * CC + ct * 32;
    for (int yy = y0; yy < 32; yy += 8)
        dst[(size_t)yy * CC + x] = t[x][yy];
}

// ------------------------------------------------------------------
// Coarse bf16 HMMA scoring (single pass, r2-free scores: es - 2*dot).
// Writes per-(row, 128-code chunk) minima; y==0 blocks also reset g_best.
__global__ __launch_bounds__(256)
void coarse_kernel(int N, int nsplit) {
    extern __shared__ unsigned sm[];
    unsigned* sA = sm;              // [256][68]
    unsigned* sB = sm + 256 * 68;   // [128][68]
    int tid = threadIdx.x, lane = tid & 31, wid = tid >> 5;
    int g = lane >> 2, t = lane & 3;
    int row0 = blockIdx.x * 256;

    const float4* rnc4 = (const float4*)g_rnc;
    for (int i = tid; i < 256 * 32; i += 256) {
        int r = i >> 5, q = i & 31;
        int rg = min(row0 + r, N - 1);
        float4 v = rnc4[(size_t)rg * 32 + q];
        sA[r * 68 + 2 * q]     = pack2(v.x, v.y);
        sA[r * 68 + 2 * q + 1] = pack2(v.z, v.w);
    }
    __syncthreads();

    unsigned a[2][8][4];
    int rl0 = wid * 32;
#pragma unroll
    for (int tile = 0; tile < 2; tile++) {
        int rb = rl0 + tile * 16;
#pragma unroll
        for (int ks = 0; ks < 8; ks++) {
            a[tile][ks][0] = sA[(rb + g    ) * 68 + ks * 8 + t];
            a[tile][ks][1] = sA[(rb + g + 8) * 68 + ks * 8 + t];
            a[tile][ks][2] = sA[(rb + g    ) * 68 + ks * 8 + t + 4];
            a[tile][ks][3] = sA[(rb + g + 8) * 68 + ks * 8 + t + 4];
        }
    }

    int rows[4];
#pragma unroll
    for (int s = 0; s < 4; s++) {
        int tile = s >> 1, half = s & 1;
        rows[s] = row0 + rl0 + tile * 16 + g + half * 8;
        if (blockIdx.y == 0 && t == 0 && rows[s] < N) g_best[rows[s]] = ~0ULL;
    }

    int cpb = NBCODE / nsplit;
    int c0s = blockIdx.y * cpb;
    const uint4* embw4 = (const uint4*)g_embw;

    for (int chunk = 0; chunk < cpb / 128; chunk++) {
        int c0 = c0s + chunk * 128;
        __syncthreads();
        for (int i = tid; i < 128 * 16; i += 256) {
            int r = i >> 4, q = i & 15;
            uint4 v = embw4[(size_t)(c0 + r) * 16 + q];
            sB[r * 68 + 4 * q]     = v.x;
            sB[r * 68 + 4 * q + 1] = v.y;
            sB[r * 68 + 4 * q + 2] = v.z;
            sB[r * 68 + 4 * q + 3] = v.w;
        }
        __syncthreads();

        float cmins[4] = {3.4e38f, 3.4e38f, 3.4e38f, 3.4e38f};
#pragma unroll 1
        for (int grp = 0; grp < 16; grp++) {
            float d0[4] = {0, 0, 0, 0}, d1[4] = {0, 0, 0, 0};
            const unsigned* brow = sB + (grp * 8 + g) * 68;
#pragma unroll
            for (int ks = 0; ks < 8; ks++) {
                unsigned b0 = brow[ks * 8 + t], b1 = brow[ks * 8 + t + 4];
                mma16816(d0, a[0][ks], b0, b1);
                mma16816(d1, a[1][ks], b0, b1);
            }
            int cc = c0 + grp * 8 + 2 * t;
            float e0 = __ldg(&g_esq[cc]), e1 = __ldg(&g_esq[cc + 1]);
            float vs[4][2] = {{d0[0], d0[1]}, {d0[2], d0[3]},
                              {d1[0], d1[1]}, {d1[2], d1[3]}};
#pragma unroll
            for (int s = 0; s < 4; s++) {
                float s0 = __fmaf_rn(-2.0f, vs[s][0], e0);
                float s1 = __fmaf_rn(-2.0f, vs[s][1], e1);
                cmins[s] = fminf(cmins[s], fminf(s0, s1));
            }
        }
        int gchunk = c0 >> 7;
#pragma unroll
        for (int s = 0; s < 4; s++) {
            float m = cmins[s];
            m = fminf(m, __shfl_xor_sync(0xFFFFFFFFu, m, 1));
            m = fminf(m, __shfl_xor_sync(0xFFFFFFFFu, m, 2));
            if (t == 0 && rows[s] < N) g_chmin[rows[s] * NCHUNK + gchunk] = m;
        }
    }
}

// fused row-min + select + exact refine. Block = (row, y-slice of chunks).
// Selection list built by DETERMINISTIC ballot/popc compaction (ordered by
// chunk id) so every y-block partitions the identical list; chunks processed
// with stride 2*gridDim.y. gridDim.y==1 -> write idx/counts directly; else
// atomicMin into g_best (commutative -> deterministic final min).
__global__ __launch_bounds__(256)
void refine_kernel(int N) {
    __shared__ float sr[128];
    __shared__ float schm[128];
    __shared__ int sel[NCHUNK];
    __shared__ int wcnt[4];
    __shared__ int scnt;
    __shared__ unsigned long long sbest;
    __shared__ float s_r2, s_cm;
    int row = blockIdx.x;
    int tid = threadIdx.x;
    int lane = tid & 31, w = tid >> 5;
    if (tid == 0) sbest = ~0ULL;
    if (tid < 128) {
        sr[tid] = g_rnc[(size_t)row * CC + tid];
        schm[tid] = g_chmin[row * NCHUNK + tid];
    }
    __syncthreads();
    if (tid == 0) {                       // sequential r2 (bitwise == old r2_kernel)
        float s = 0.0f;
#pragma unroll 8
        for (int d = 0; d < CC; d++) s = fmaf(sr[d], sr[d], s);
        s_r2 = s;
    }
    if (w == 1) {                         // warp 1: min over 128 chunk minima
        float m = fminf(fminf(schm[lane], schm[lane + 32]),
                        fminf(schm[lane + 64], schm[lane + 96]));
#pragma unroll
        for (int o = 16; o > 0; o >>= 1) m = fminf(m, __shfl_xor_sync(0xFFFFFFFFu, m, o));
        if (lane == 0) s_cm = m;
    }
    __syncthreads();
    float r2v = s_r2;
    float emax = __int_as_float(g_esqmax);
    float thr = s_cm + 0.0320f * sqrtf(r2v * emax) + 2e-3f;

    // deterministic ordered compaction of selected chunks (tid < 128)
    bool pick = (tid < NCHUNK) && (schm[tid] <= thr);
    unsigned bal = __ballot_sync(0xFFFFFFFFu, pick);
    if (w < 4 && lane == 0) wcnt[w] = __popc(bal);
    __syncthreads();
    if (pick) {
        int base = 0;
        for (int ww = 0; ww < w; ww++) base += wcnt[ww];
        int pos = base + __popc(bal & ((1u << lane) - 1u));
        sel[pos] = tid;
    }
    if (tid == 0) scnt = wcnt[0] + wcnt[1] + wcnt[2] + wcnt[3];
    __syncthreads();

    unsigned long long best = ~0ULL;
    int half = tid >> 7, t = tid & 127;
    int cnt = scnt;
    int stride = 2 * gridDim.y;
    for (int s = 2 * blockIdx.y + half; s < cnt; s += stride) {
        int code = sel[s] * 128 + t;
        const float* ep = g_embT + code;
        float p0 = 0.f, p1 = 0.f, p2 = 0.f, p3 = 0.f;
#pragma unroll 8
        for (int d = 0; d < 128; d += 4) {
            p0 = __fmaf_rn(sr[d],     ep[(size_t)(d)     * NBCODE], p0);
            p1 = __fmaf_rn(sr[d + 1], ep[(size_t)(d + 1) * NBCODE], p1);
            p2 = __fmaf_rn(sr[d + 2], ep[(size_t)(d + 2) * NBCODE], p2);
            p3 = __fmaf_rn(sr[d + 3], ep[(size_t)(d + 3) * NBCODE], p3);
        }
        float dot = (p0 + p1) + (p2 + p3);
        float tt = __fadd_rn(r2v, __ldg(&g_esq[code]));   // round(r2 + e_sq)
        float sc = __fsub_rn(tt, 2.0f * dot);             // round(t - 2*dot)
        unsigned long long key = ((unsigned long long)fkey(sc) << 32) | (unsigned)code;
        if (key < best) best = key;
    }
    atomicMin(&sbest, best);
    __syncthreads();
    if (tid == 0) {
        if (gridDim.y == 1) {
            int idx = (int)(unsigned)(sbest & 0xFFFFFFFFull);
            g_idx[row] = idx;
            atomicAdd(&g_counts[idx], 1);
        } else if (sbest != ~0ULL) {
            atomicMin(&g_best[row], sbest);
        }
    }
}

__global__ void fill_idx(int N) {
    int n = blockIdx.x * blockDim.x + threadIdx.x;
    if (n >= N) return;
    int idx = (int)(unsigned)(g_best[n] & 0xFFFFFFFFull);
    g_idx[n] = idx;
    atomicAdd(&g_counts[idx], 1);
}

// ------------------------------------------------------------------
__device__ __forceinline__ float cubicw(float x) {
    const float a = -0.75f;
    float ax = fabsf(x);
    if (ax <= 1.0f) return ((a + 2.0f) * ax - (a + 3.0f)) * ax * ax + 1.0f;
    if (ax < 2.0f)  return a * (((ax - 5.0f) * ax + 8.0f) * ax - 4.0f);
    return 0.0f;
}

// smem-tiled bicubic upsample (sn < 16)
__global__ __launch_bounds__(256)
void upsample_kernel(const float* __restrict__ emb, int sn) {
    __shared__ float sT[32][130];
    int b   = blockIdx.x >> 3;
    int pxg = (blockIdx.x & 7) * 32;
    int tid = threadIdx.x;
    float scale = (float)sn / 16.0f;
    int c2 = (tid & 63) * 2;
    int pxl0 = tid >> 6;

#pragma unroll 2
    for (int p = 0; p < 8; p++) {
        int pxl = pxl0 * 8 + p;
        int px = pxg + pxl;
        int l = px & 15, j = px >> 4;
        float xj = (j + 0.5f) * scale - 0.5f;
        int x0j = (int)floorf(xj);
        float tj = xj - (float)x0j;
        float xl = (l + 0.5f) * scale - 0.5f;
        int x0l = (int)floorf(xl);
        float tl = xl - (float)x0l;
        float a0 = 0.f, a1 = 0.f;
#pragma unroll
        for (int kj = 0; kj < 4; kj++) {
            float wj = cubicw(tj + 1.0f - (float)kj);
            int sj = min(max(x0j - 1 + kj, 0), sn - 1);
#pragma unroll
            for (int kl = 0; kl < 4; kl++) {
                float wl = cubicw(tl + 1.0f - (float)kl);
                int sl = min(max(x0l - 1 + kl, 0), sn - 1);
                int n = (b * sn + sj) * sn + sl;
                const float2 e = *(const float2*)(emb + (size_t)g_idx[n] * CC + c2);
                float w = wj * wl;
                a0 += w * e.x;
                a1 += w * e.y;
            }
        }
        sT[pxl][c2] = a0;
        sT[pxl][c2 + 1] = a1;
    }
    __syncthreads();
    int c = tid >> 1, half = tid & 1;
    float* dst = g_hs + ((size_t)(b * CC + c)) * 256 + pxg + half * 16;
#pragma unroll
    for (int i = 0; i < 16; i += 4) {
        float4 v = make_float4(sT[half * 16 + i][c], sT[half * 16 + i + 1][c],
                               sT[half * 16 + i + 2][c], sT[half * 16 + i + 3][c]);
        *(float4*)(dst + i) = v;
    }
}

// sn == 16: identity -> coalesced gather + transpose
__global__ void gather16_kernel(const float* __restrict__ emb) {
    __shared__ float s[32 * 133];
    int tid = threadIdx.x;
    int lane = tid & 31, w = tid >> 5;
    int b  = blockIdx.x >> 3;
    int n0 = (blockIdx.x & 7) * 32;

    const float4* emb4 = (const float4*)emb;
#pragma unroll
    for (int st = 0; st < 4; st++) {
        int i = w * 4 + st;
        int idx = g_idx[b * 256 + n0 + i];
        float4 v = emb4[(size_t)idx * 32 + lane];
        s[i * 133 + lane * 4 + 0] = v.x;
        s[i * 133 + lane * 4 + 1] = v.y;
        s[i * 133 + lane * 4 + 2] = v.z;
        s[i * 133 + lane * 4 + 3] = v.w;
    }
    __syncthreads();
#pragma unroll
    for (int it = 0; it < 16; it++) {
        int c = w + it * 8;
        g_hs[(((size_t)b * 128 + c) << 8) + n0 + lane] = s[lane * 133 + c];
    }
}

// ------------------------------------------------------------------
// conv3x3 + bias as 9 shifted GEMMs on bf16 HMMA, 2-limb split
// (AhWh + AlWh + AhWl). Epilogue: phi blend, f_hat/f_rest, loss.
__global__ __launch_bounds__(512, 1)
void conv_mma_kernel(const float* __restrict__ w, const float* __restrict__ bias,
                     const float* __restrict__ f_in, float* __restrict__ fhat) {
    extern __shared__ unsigned csm[];
    unsigned* sAh = csm;                    // [256][67]
    unsigned* sAl = csm + 256 * 67;
    unsigned* sWh = csm + 2 * 256 * 67;     // [16][577]
    unsigned* sWl = sWh + 16 * 577;

    int b = blockIdx.x >> 3;
    int cobase = (blockIdx.x & 7) * 16;
    int tid = threadIdx.x;
    int lane = tid & 31, wid = tid >> 5;
    int g = lane >> 2, t = lane & 3;

    const float* hsb = g_hs + (size_t)b * CC * 256;
    for (int i = tid; i < 64 * 256; i += 512) {
        int px = i & 255, wd = i >> 8;
        float h0 = hsb[(2 * wd) * 256 + px];
        float h1 = hsb[(2 * wd + 1) * 256 + px];
        float h0h = __bfloat162float(__float2bfloat16(h0));
        float h1h = __bfloat162float(__float2bfloat16(h1));
        sAh[px * 67 + wd] = pack2(h0, h1);
        sAl[px * 67 + wd] = pack2(h0 - h0h, h1 - h1h);
    }
    __nv_bfloat16* sWhb = (__nv_bfloat16*)sWh;
    __nv_bfloat16* sWlb = (__nv_bfloat16*)sWl;
    for (int i = tid; i < 16 * 128 * 9; i += 512) {
        int q = i % 9; int ci = (i / 9) & 127; int co = i / (9 * 128);
        float wv = w[((size_t)(cobase + co) * CC + ci) * 9 + q];
        float wh = __bfloat162float(__float2bfloat16(wv));
        sWhb[(size_t)co * 1154 + q * 128 + ci] = __float2bfloat16(wv);
        sWlb[(size_t)co * 1154 + q * 128 + ci] = __float2bfloat16(wv - wh);
    }
    __syncthreads();

    float d[2][4];
#pragma unroll
    for (int nt = 0; nt < 2; nt++) {
        float bv0 = bias[cobase + nt * 8 + 2 * t];
        float bv1 = bias[cobase + nt * 8 + 2 * t + 1];
        d[nt][0] = bv0; d[nt][1] = bv1; d[nt][2] = bv0; d[nt][3] = bv1;
    }

#pragma unroll
    for (int combo = 0; combo < 3; combo++) {
        const unsigned* A = (combo == 1) ? sAl : sAh;
        const unsigned* W = (combo == 2) ? sWl : sWh;
#pragma unroll 1
        for (int q = 0; q < 9; q++) {
            int dj = q / 3 - 1, dl = q % 3 - 1;
            bool jv = (unsigned)(wid + dj) < 16u;
            bool p0 = jv && ((unsigned)(g + dl) < 16u);
            bool p1 = jv && ((unsigned)(g + 8 + dl) < 16u);
            int sr0 = min(max(wid * 16 + g + dj * 16 + dl, 0), 255);
            int sr1 = min(max(wid * 16 + g + 8 + dj * 16 + dl, 0), 255);
            unsigned a[8][4];
#pragma unroll
            for (int ks = 0; ks < 8; ks++) {
                int w0 = ks * 8 + t;
                a[ks][0] = p0 ? A[sr0 * 67 + w0] : 0u;
                a[ks][1] = p1 ? A[sr1 * 67 + w0] : 0u;
                a[ks][2] = p0 ? A[sr0 * 67 + w0 + 4] : 0u;
                a[ks][3] = p1 ? A[sr1 * 67 + w0 + 4] : 0u;
            }
#pragma unroll
            for (int nt = 0; nt < 2; nt++) {
                const unsigned* brow = W + (nt * 8 + g) * 577 + q * 64;
#pragma unroll
                for (int ks = 0; ks < 8; ks++) {
                    mma16816(d[nt], a[ks], brow[ks * 8 + t], brow[ks * 8 + t + 4]);
                }
            }
        }
    }

    float lsum = 0.f;
#pragma unroll
    for (int nt = 0; nt < 2; nt++) {
#pragma unroll
        for (int r = 0; r < 4; r++) {
            int px = wid * 16 + g + ((r >= 2) ? 8 : 0);
            int co = cobase + nt * 8 + 2 * t + (r & 1);
            size_t gi = ((size_t)(b * CC + co) << 8) + px;
            float h = 0.5f * g_hs[gi] + 0.5f * d[nt][r];
            float fh = fhat[gi] + h;
            fhat[gi] = fh;
            g_frest[gi] -= h;
            float df = fh - f_in[gi];
            lsum += df * df;
        }
    }
#pragma unroll
    for (int o = 16; o > 0; o >>= 1) lsum += __shfl_xor_sync(0xFFFFFFFFu, lsum, o);
    if (lane == 0) atomicAdd(&g_loss, lsum * (0.25f / (float)FHN));
}

__global__ void final_kernel(float* __restrict__ out) {
    __shared__ float red[256];
    int tid = threadIdx.x;
    float s = 0.0f;
    for (int k = tid; k < NBCODE; k += 256) {
        float p = (float)g_counts[k] * (1.0f / (float)NTOT);
        s += p * logf(p + 1e-10f);
    }
    red[tid] = s;
    __syncthreads();
    for (int st = 128; st > 0; st >>= 1) {
        if (tid < st) red[tid] += red[tid + st];
        __syncthreads();
    }
    if (tid == 0) {
        out[FHN]     = g_loss;
        out[FHN + 1] = expf(-red[0]);
    }
}

// ------------------------------------------------------------------
extern "C" void kernel_launch(void* const* d_in, const int* in_sizes, int n_in,
                              void* d_out, int out_size) {
    const float* f     = (const float*)d_in[0];
    const float* emb   = (const float*)d_in[1];
    const float* phi_w = (const float*)d_in[2];
    const float* phi_b = (const float*)d_in[3];
    float* out = (float*)d_out;

    cudaFuncSetAttribute(coarse_kernel, cudaFuncAttributeMaxDynamicSharedMemorySize, CO_SMEM);
    cudaFuncSetAttribute(conv_mma_kernel, cudaFuncAttributeMaxDynamicSharedMemorySize, CONV_SMEM);

    prep_all<<<8256, 256>>>(f, out, emb);

    const int sns[5]     = {1, 2, 4, 8, 16};
    const int phis[5]    = {0, 1, 1, 2, 3};
    const int splits[5]  = {128, 128, 128, 64, 16};
    const int rsplit[5]  = {8, 8, 4, 2, 1};
    for (int si = 0; si < 5; si++) {
        int sn = sns[si];
        int N = BB * sn * sn;
        int fct = 16 / sn;
        int nsplit = splits[si];
        if (sn == 1) {
            pool16_kernel<<<256, 256>>>();
        } else if (sn == 2) {
            pool8_kernel<<<1024, 256>>>();
        } else if (sn == 16) {
            pool1_kernel<<<512, 256>>>();
        } else {
            pool_kernel<<<(N * CC + 255) / 256, 256>>>(sn, fct);
        }
        dim3 g((N + 255) / 256, nsplit);
        coarse_kernel<<<g, 256, CO_SMEM>>>(N, nsplit);
        dim3 rg(N, rsplit[si]);
        refine_kernel<<<rg, 256>>>(N);
        if (rsplit[si] > 1) fill_idx<<<(N + 255) / 256, 256>>>(N);
        if (sn == 16) {
            gather16_kernel<<<128, 256>>>(emb);
        } else {
            upsample_kernel<<<128, 256>>>(emb, sn);
        }
        int k = phis[si];
        conv_mma_kernel<<<128, 512, CONV_SMEM>>>(phi_w + (size_t)k * CC * CC * 9,
                                                 phi_b + (size_t)k * CC, f, out);
    }
    final_kernel<<<1, 256>>>(out);
}

// round 13
// speedup vs baseline: 1.4423x; 1.4423x over previous
#include <cuda_runtime.h>
#include <cuda_bf16.h>
#include <math.h>

#define BB 16
#define CC 128
#define NBCODE 16384
#define NTOT 5456
#define FHN (BB*CC*16*16)   // 524288
#define NCHUNK 128          // 128 codes per chunk
#define CO_SMEM ((256*68 + 128*68)*4)               // 104448 bytes
#define CONV_SMEM ((2*256*67 + 2*16*577)*4)         // 211072 bytes

// ---- device scratch (no allocations allowed) ----
__device__ float g_frest[FHN];
__device__ float g_rnc[4096*CC];
__device__ float g_hs[FHN];
__device__ float g_chmin[4096*NCHUNK];
__device__ int g_idx[4096];
__device__ int g_counts[NBCODE];
__device__ float g_loss;
__device__ float g_esq[NBCODE];
__device__ int g_esqmax = 0;                  // monotone; no per-call reset needed
__device__ unsigned g_embw[NBCODE*64];        // bf16x2 words [code][64]
__device__ float g_embT[CC*NBCODE];           // transposed fp32 codebook [d][code]

// ------------------------------------------------------------------
__device__ __forceinline__ void mma16816(float* d, const unsigned* a, unsigned b0, unsigned b1) {
    asm volatile("mma.sync.aligned.m16n8k16.row.col.f32.bf16.bf16.f32 "
                 "{%0,%1,%2,%3}, {%4,%5,%6,%7}, {%8,%9}, {%0,%1,%2,%3};"
                 : "+f"(d[0]), "+f"(d[1]), "+f"(d[2]), "+f"(d[3])
                 : "r"(a[0]), "r"(a[1]), "r"(a[2]), "r"(a[3]), "r"(b0), "r"(b1));
}
__device__ __forceinline__ unsigned fkey(float f) {
    unsigned u = __float_as_uint(f);
    return (u & 0x80000000u) ? ~u : (u | 0x80000000u);
}
__device__ __forceinline__ unsigned pack2(float a, float b) {
    __nv_bfloat162 t = __floats2bfloat162_rn(a, b);
    return *(unsigned*)&t;
}

// ------------------------------------------------------------------
// Fused one-time prep: [0,2048) init, [2048,2112) esq, [2112,6208) pack,
// [6208,8256) 32x32 transpose tiles.
__global__ void prep_all(const float* __restrict__ f, float* __restrict__ fhat,
                         const float* __restrict__ emb) {
    __shared__ float t[32][33];
    int blk = blockIdx.x, tid = threadIdx.x;
    if (blk < 2048) {
        int i = blk * 256 + tid;
        fhat[i] = 0.0f;
        g_frest[i] = f[i];
        if (i < NBCODE) g_counts[i] = 0;
        if (i == 0) g_loss = 0.0f;
    } else if (blk < 2112) {
        int k = (blk - 2048) * 256 + tid;
        const float* e = emb + (size_t)k * CC;
        float s = 0.0f;
#pragma unroll 8
        for (int d = 0; d < CC; d++) s = fmaf(e[d], e[d], s);
        g_esq[k] = s;
        atomicMax(&g_esqmax, __float_as_int(s));   // s>=0: int order == float order
    } else if (blk < 6208) {
        int i = (blk - 2112) * 256 + tid;          // NBCODE*64 words
        float2 v = ((const float2*)emb)[i];
        g_embw[i] = pack2(v.x, v.y);
    } else {
        int idx = blk - 6208;                      // 2048 tiles
        int k0 = (idx & 511) * 32, d0 = (idx >> 9) * 32;
        int x = tid & 31, y0 = tid >> 5;
        for (int yy = y0; yy < 32; yy += 8)
            t[yy][x] = emb[(size_t)(k0 + yy) * CC + d0 + x];
        __syncthreads();
        for (int yy = y0; yy < 32; yy += 8)
            g_embT[(size_t)(d0 + yy) * NBCODE + k0 + x] = t[x][yy];
    }
}

// thread-per-output pooling (fct = 2,4)
__global__ void pool_kernel(int sn, int fct) {
    int i = blockIdx.x * blockDim.x + threadIdx.x;
    int N = BB * sn * sn;
    if (i >= N * CC) return;
    int n = i / CC, c = i % CC;
    int t = n % sn;
    int s = (n / sn) % sn;
    int b = n / (sn * sn);
    const float* base = g_frest + ((size_t)(b * CC + c)) * 256;
    float acc = 0.0f;
    for (int dj = 0; dj < fct; dj++)
        for (int dl = 0; dl < fct; dl++)
            acc += base[(s * fct + dj) * 16 + (t * fct + dl)];
    g_rnc[n * CC + c] = acc * (1.0f / (float)(fct * fct));
}

// warp-per-output pooling, fct=16 (sn=1)
__global__ void pool16_kernel() {
    int out = blockIdx.x * 8 + (threadIdx.x >> 5);
    int lane = threadIdx.x & 31;
    const float4* base = (const float4*)(g_frest + (size_t)out * 256);
    float4 v1 = base[lane], v2 = base[lane + 32];
    float s = v1.x + v1.y + v1.z + v1.w + v2.x + v2.y + v2.z + v2.w;
#pragma unroll
    for (int o = 16; o > 0; o >>= 1) s += __shfl_xor_sync(0xFFFFFFFFu, s, o);
    if (lane == 0) g_rnc[out] = s * (1.0f / 256.0f);
}

// warp-per-output pooling, fct=8 (sn=2)
__global__ void pool8_kernel() {
    int out = blockIdx.x * 8 + (threadIdx.x >> 5);
    int lane = threadIdx.x & 31;
    int n = out >> 7, c = out & 127;
    int t = n & 1, s = (n >> 1) & 1, b = n >> 2;
    const float* base = g_frest + ((size_t)(b * CC + c)) * 256;
    int dj = lane >> 2, dl = (lane & 3) * 2;
    const float2* p = (const float2*)(base + (s * 8 + dj) * 16 + t * 8 + dl);
    float2 v = *p;
    float sm = v.x + v.y;
#pragma unroll
    for (int o = 16; o > 0; o >>= 1) sm += __shfl_xor_sync(0xFFFFFFFFu, sm, o);
    if (lane == 0) g_rnc[out] = sm * (1.0f / 64.0f);
}

// sn=16 "pool" = identity transpose, coalesced both ways via 32x32 tiles
__global__ void pool1_kernel() {
    __shared__ float t[32][33];
    int b  = blockIdx.x >> 5;
    int ct = (blockIdx.x >> 3) & 3;
    int pt = blockIdx.x & 7;
    int x = threadIdx.x & 31, y0 = threadIdx.x >> 5;
    const float* src = g_frest + ((size_t)(b * CC + ct * 32)) * 256 + pt * 32;
    for (int yy = y0; yy < 32; yy += 8)
        t[yy][x] = src[(size_t)yy * 256 + x];
    __syncthreads();
    float* dst = g_rnc + ((size_t)(b * 256 + pt * 32)) * CC + ct * 32;
    for (int yy = y0; yy < 32; yy += 8)
        dst[(size_t)yy * CC + x] = t[x][yy];
}

// ------------------------------------------------------------------
// Coarse bf16 HMMA scoring (single pass, r2-free scores: es - 2*dot).
// Writes per-(row, 128-code chunk) minima.
__global__ __launch_bounds__(256)
void coarse_kernel(int N, int nsplit) {
    extern __shared__ unsigned sm[];
    unsigned* sA = sm;              // [256][68]
    unsigned* sB = sm + 256 * 68;   // [128][68]
    int tid = threadIdx.x, lane = tid & 31, wid = tid >> 5;
    int g = lane >> 2, t = lane & 3;
    int row0 = blockIdx.x * 256;

    const float4* rnc4 = (const float4*)g_rnc;
    for (int i = tid; i < 256 * 32; i += 256) {
        int r = i >> 5, q = i & 31;
        int rg = min(row0 + r, N - 1);
        float4 v = rnc4[(size_t)rg * 32 + q];
        sA[r * 68 + 2 * q]     = pack2(v.x, v.y);
        sA[r * 68 + 2 * q + 1] = pack2(v.z, v.w);
    }
    __syncthreads();

    unsigned a[2][8][4];
    int rl0 = wid * 32;
#pragma unroll
    for (int tile = 0; tile < 2; tile++) {
        int rb = rl0 + tile * 16;
#pragma unroll
        for (int ks = 0; ks < 8; ks++) {
            a[tile][ks][0] = sA[(rb + g    ) * 68 + ks * 8 + t];
            a[tile][ks][1] = sA[(rb + g + 8) * 68 + ks * 8 + t];
            a[tile][ks][2] = sA[(rb + g    ) * 68 + ks * 8 + t + 4];
            a[tile][ks][3] = sA[(rb + g + 8) * 68 + ks * 8 + t + 4];
        }
    }

    int rows[4];
#pragma unroll
    for (int s = 0; s < 4; s++) {
        int tile = s >> 1, half = s & 1;
        rows[s] = row0 + rl0 + tile * 16 + g + half * 8;
    }

    int cpb = NBCODE / nsplit;
    int c0s = blockIdx.y * cpb;
    const uint4* embw4 = (const uint4*)g_embw;

    for (int chunk = 0; chunk < cpb / 128; chunk++) {
        int c0 = c0s + chunk * 128;
        __syncthreads();
        for (int i = tid; i < 128 * 16; i += 256) {
            int r = i >> 4, q = i & 15;
            uint4 v = embw4[(size_t)(c0 + r) * 16 + q];
            sB[r * 68 + 4 * q]     = v.x;
            sB[r * 68 + 4 * q + 1] = v.y;
            sB[r * 68 + 4 * q + 2] = v.z;
            sB[r * 68 + 4 * q + 3] = v.w;
        }
        __syncthreads();

        float cmins[4] = {3.4e38f, 3.4e38f, 3.4e38f, 3.4e38f};
#pragma unroll 1
        for (int grp = 0; grp < 16; grp++) {
            float d0[4] = {0, 0, 0, 0}, d1[4] = {0, 0, 0, 0};
            const unsigned* brow = sB + (grp * 8 + g) * 68;
#pragma unroll
            for (int ks = 0; ks < 8; ks++) {
                unsigned b0 = brow[ks * 8 + t], b1 = brow[ks * 8 + t + 4];
                mma16816(d0, a[0][ks], b0, b1);
                mma16816(d1, a[1][ks], b0, b1);
            }
            int cc = c0 + grp * 8 + 2 * t;
            float e0 = __ldg(&g_esq[cc]), e1 = __ldg(&g_esq[cc + 1]);
            float vs[4][2] = {{d0[0], d0[1]}, {d0[2], d0[3]},
                              {d1[0], d1[1]}, {d1[2], d1[3]}};
#pragma unroll
            for (int s = 0; s < 4; s++) {
                float s0 = __fmaf_rn(-2.0f, vs[s][0], e0);
                float s1 = __fmaf_rn(-2.0f, vs[s][1], e1);
                cmins[s] = fminf(cmins[s], fminf(s0, s1));
            }
        }
        int gchunk = c0 >> 7;
#pragma unroll
        for (int s = 0; s < 4; s++) {
            float m = cmins[s];
            m = fminf(m, __shfl_xor_sync(0xFFFFFFFFu, m, 1));
            m = fminf(m, __shfl_xor_sync(0xFFFFFFFFu, m, 2));
            if (t == 0 && rows[s] < N) g_chmin[rows[s] * NCHUNK + gchunk] = m;
        }
    }
}

// fused row-min + select + exact refine + index/count. One block per row.
// Deterministic ballot/popc compaction; per-thread 2-chunk ILP (dual 4-chain
// accumulators) to halve the dependent-latency serial depth at small N.
__global__ __launch_bounds__(256)
void refine_kernel(int N) {
    __shared__ float sr[128];
    __shared__ float schm[128];
    __shared__ int sel[NCHUNK];
    __shared__ int wcnt[4];
    __shared__ int scnt;
    __shared__ unsigned long long sbest;
    __shared__ float s_r2, s_cm;
    int row = blockIdx.x;
    int tid = threadIdx.x;
    int lane = tid & 31, w = tid >> 5;
    if (tid == 0) sbest = ~0ULL;
    if (tid < 128) {
        sr[tid] = g_rnc[(size_t)row * CC + tid];
        schm[tid] = g_chmin[row * NCHUNK + tid];
    }
    __syncthreads();
    if (tid == 0) {                       // sequential r2 (bitwise == old r2_kernel)
        float s = 0.0f;
#pragma unroll 8
        for (int d = 0; d < CC; d++) s = fmaf(sr[d], sr[d], s);
        s_r2 = s;
    }
    if (w == 1) {                         // warp 1: min over 128 chunk minima
        float m = fminf(fminf(schm[lane], schm[lane + 32]),
                        fminf(schm[lane + 64], schm[lane + 96]));
#pragma unroll
        for (int o = 16; o > 0; o >>= 1) m = fminf(m, __shfl_xor_sync(0xFFFFFFFFu, m, o));
        if (lane == 0) s_cm = m;
    }
    __syncthreads();
    float r2v = s_r2;
    float emax = __int_as_float(g_esqmax);
    float thr = s_cm + 0.0320f * sqrtf(r2v * emax) + 2e-3f;

    // deterministic ordered compaction of selected chunks (tid < 128)
    bool pick = (tid < NCHUNK) && (schm[tid] <= thr);
    unsigned bal = __ballot_sync(0xFFFFFFFFu, pick);
    if (w < 4 && lane == 0) wcnt[w] = __popc(bal);
    __syncthreads();
    if (pick) {
        int base = 0;
        for (int ww = 0; ww < w; ww++) base += wcnt[ww];
        int pos = base + __popc(bal & ((1u << lane) - 1u));
        sel[pos] = tid;
    }
    if (tid == 0) scnt = wcnt[0] + wcnt[1] + wcnt[2] + wcnt[3];
    __syncthreads();

    unsigned long long best = ~0ULL;
    int half = tid >> 7, t = tid & 127;
    int cnt = scnt;
    int s = half;
    // 2 chunks per iteration (8 independent fmaf chains -> 2x MLP)
    for (; s + 2 < cnt; s += 4) {
        int codeA = sel[s] * 128 + t;
        int codeB = sel[s + 2] * 128 + t;
        const float* epA = g_embT + codeA;
        const float* epB = g_embT + codeB;
        float a0 = 0.f, a1 = 0.f, a2 = 0.f, a3 = 0.f;
        float b0 = 0.f, b1 = 0.f, b2 = 0.f, b3 = 0.f;
#pragma unroll 4
        for (int d = 0; d < 128; d += 4) {
            a0 = __fmaf_rn(sr[d],     epA[(size_t)(d)     * NBCODE], a0);
            b0 = __fmaf_rn(sr[d],     epB[(size_t)(d)     * NBCODE], b0);
            a1 = __fmaf_rn(sr[d + 1], epA[(size_t)(d + 1) * NBCODE], a1);
            b1 = __fmaf_rn(sr[d + 1], epB[(size_t)(d + 1) * NBCODE], b1);
            a2 = __fmaf_rn(sr[d + 2], epA[(size_t)(d + 2) * NBCODE], a2);
            b2 = __fmaf_rn(sr[d + 2], epB[(size_t)(d + 2) * NBCODE], b2);
            a3 = __fmaf_rn(sr[d + 3], epA[(size_t)(d + 3) * NBCODE], a3);
            b3 = __fmaf_rn(sr[d + 3], epB[(size_t)(d + 3) * NBCODE], b3);
        }
        float dotA = (a0 + a1) + (a2 + a3);
        float dotB = (b0 + b1) + (b2 + b3);
        float ttA = __fadd_rn(r2v, __ldg(&g_esq[codeA]));
        float scA = __fsub_rn(ttA, 2.0f * dotA);
        unsigned long long keyA = ((unsigned long long)fkey(scA) << 32) | (unsigned)codeA;
        if (keyA < best) best = keyA;
        float ttB = __fadd_rn(r2v, __ldg(&g_esq[codeB]));
        float scB = __fsub_rn(ttB, 2.0f * dotB);
        unsigned long long keyB = ((unsigned long long)fkey(scB) << 32) | (unsigned)codeB;
        if (keyB < best) best = keyB;
    }
    if (s < cnt) {
        int code = sel[s] * 128 + t;
        const float* ep = g_embT + code;
        float p0 = 0.f, p1 = 0.f, p2 = 0.f, p3 = 0.f;
#pragma unroll 8
        for (int d = 0; d < 128; d += 4) {
            p0 = __fmaf_rn(sr[d],     ep[(size_t)(d)     * NBCODE], p0);
            p1 = __fmaf_rn(sr[d + 1], ep[(size_t)(d + 1) * NBCODE], p1);
            p2 = __fmaf_rn(sr[d + 2], ep[(size_t)(d + 2) * NBCODE], p2);
            p3 = __fmaf_rn(sr[d + 3], ep[(size_t)(d + 3) * NBCODE], p3);
        }
        float dot = (p0 + p1) + (p2 + p3);
        float tt = __fadd_rn(r2v, __ldg(&g_esq[code]));   // round(r2 + e_sq)
        float sc = __fsub_rn(tt, 2.0f * dot);             // round(t - 2*dot)
        unsigned long long key = ((unsigned long long)fkey(sc) << 32) | (unsigned)code;
        if (key < best) best = key;
    }
    atomicMin(&sbest, best);
    __syncthreads();
    if (tid == 0) {
        int idx = (int)(unsigned)(sbest & 0xFFFFFFFFull);
        g_idx[row] = idx;
        atomicAdd(&g_counts[idx], 1);
    }
}

// ------------------------------------------------------------------
__device__ __forceinline__ float cubicw(float x) {
    const float a = -0.75f;
    float ax = fabsf(x);
    if (ax <= 1.0f) return ((a + 2.0f) * ax - (a + 3.0f)) * ax * ax + 1.0f;
    if (ax < 2.0f)  return a * (((ax - 5.0f) * ax + 8.0f) * ax - 4.0f);
    return 0.0f;
}

// smem-tiled bicubic upsample (sn < 16)
__global__ __launch_bounds__(256)
void upsample_kernel(const float* __restrict__ emb, int sn) {
    __shared__ float sT[32][130];
    int b   = blockIdx.x >> 3;
    int pxg = (blockIdx.x & 7) * 32;
    int tid = threadIdx.x;
    float scale = (float)sn / 16.0f;
    int c2 = (tid & 63) * 2;
    int pxl0 = tid >> 6;

#pragma unroll 2
    for (int p = 0; p < 8; p++) {
        int pxl = pxl0 * 8 + p;
        int px = pxg + pxl;
        int l = px & 15, j = px >> 4;
        float xj = (j + 0.5f) * scale - 0.5f;
        int x0j = (int)floorf(xj);
        float tj = xj - (float)x0j;
        float xl = (l + 0.5f) * scale - 0.5f;
        int x0l = (int)floorf(xl);
        float tl = xl - (float)x0l;
        float a0 = 0.f, a1 = 0.f;
#pragma unroll
        for (int kj = 0; kj < 4; kj++) {
            float wj = cubicw(tj + 1.0f - (float)kj);
            int sj = min(max(x0j - 1 + kj, 0), sn - 1);
#pragma unroll
            for (int kl = 0; kl < 4; kl++) {
                float wl = cubicw(tl + 1.0f - (float)kl);
                int sl = min(max(x0l - 1 + kl, 0), sn - 1);
                int n = (b * sn + sj) * sn + sl;
                const float2 e = *(const float2*)(emb + (size_t)g_idx[n] * CC + c2);
                float w = wj * wl;
                a0 += w * e.x;
                a1 += w * e.y;
            }
        }
        sT[pxl][c2] = a0;
        sT[pxl][c2 + 1] = a1;
    }
    __syncthreads();
    int c = tid >> 1, half = tid & 1;
    float* dst = g_hs + ((size_t)(b * CC + c)) * 256 + pxg + half * 16;
#pragma unroll
    for (int i = 0; i < 16; i += 4) {
        float4 v = make_float4(sT[half * 16 + i][c], sT[half * 16 + i + 1][c],
                               sT[half * 16 + i + 2][c], sT[half * 16 + i + 3][c]);
        *(float4*)(dst + i) = v;
    }
}

// sn == 16: identity -> coalesced gather + transpose
__global__ void gather16_kernel(const float* __restrict__ emb) {
    __shared__ float s[32 * 133];
    int tid = threadIdx.x;
    int lane = tid & 31, w = tid >> 5;
    int b  = blockIdx.x >> 3;
    int n0 = (blockIdx.x & 7) * 32;

    const float4* emb4 = (const float4*)emb;
#pragma unroll
    for (int st = 0; st < 4; st++) {
        int i = w * 4 + st;
        int idx = g_idx[b * 256 + n0 + i];
        float4 v = emb4[(size_t)idx * 32 + lane];
        s[i * 133 + lane * 4 + 0] = v.x;
        s[i * 133 + lane * 4 + 1] = v.y;
        s[i * 133 + lane * 4 + 2] = v.z;
        s[i * 133 + lane * 4 + 3] = v.w;
    }
    __syncthreads();
#pragma unroll
    for (int it = 0; it < 16; it++) {
        int c = w + it * 8;
        g_hs[(((size_t)b * 128 + c) << 8) + n0 + lane] = s[lane * 133 + c];
    }
}

// ------------------------------------------------------------------
// conv3x3 + bias as 9 shifted GEMMs on bf16 HMMA, 2-limb split
// (AhWh + AlWh + AhWl). Epilogue: phi blend, f_hat/f_rest, loss.
__global__ __launch_bounds__(512, 1)
void conv_mma_kernel(const float* __restrict__ w, const float* __restrict__ bias,
                     const float* __restrict__ f_in, float* __restrict__ fhat) {
    extern __shared__ unsigned csm[];
    unsigned* sAh = csm;                    // [256][67]
    unsigned* sAl = csm + 256 * 67;
    unsigned* sWh = csm + 2 * 256 * 67;     // [16][577]
    unsigned* sWl = sWh + 16 * 577;

    int b = blockIdx.x >> 3;
    int cobase = (blockIdx.x & 7) * 16;
    int tid = threadIdx.x;
    int lane = tid & 31, wid = tid >> 5;
    int g = lane >> 2, t = lane & 3;

    const float* hsb = g_hs + (size_t)b * CC * 256;
    for (int i = tid; i < 64 * 256; i += 512) {
        int px = i & 255, wd = i >> 8;
        float h0 = hsb[(2 * wd) * 256 + px];
        float h1 = hsb[(2 * wd + 1) * 256 + px];
        float h0h = __bfloat162float(__float2bfloat16(h0));
        float h1h = __bfloat162float(__float2bfloat16(h1));
        sAh[px * 67 + wd] = pack2(h0, h1);
        sAl[px * 67 + wd] = pack2(h0 - h0h, h1 - h1h);
    }
    __nv_bfloat16* sWhb = (__nv_bfloat16*)sWh;
    __nv_bfloat16* sWlb = (__nv_bfloat16*)sWl;
    for (int i = tid; i < 16 * 128 * 9; i += 512) {
        int q = i % 9; int ci = (i / 9) & 127; int co = i / (9 * 128);
        float wv = w[((size_t)(cobase + co) * CC + ci) * 9 + q];
        float wh = __bfloat162float(__float2bfloat16(wv));
        sWhb[(size_t)co * 1154 + q * 128 + ci] = __float2bfloat16(wv);
        sWlb[(size_t)co * 1154 + q * 128 + ci] = __float2bfloat16(wv - wh);
    }
    __syncthreads();

    float d[2][4];
#pragma unroll
    for (int nt = 0; nt < 2; nt++) {
        float bv0 = bias[cobase + nt * 8 + 2 * t];
        float bv1 = bias[cobase + nt * 8 + 2 * t + 1];
        d[nt][0] = bv0; d[nt][1] = bv1; d[nt][2] = bv0; d[nt][3] = bv1;
    }

#pragma unroll
    for (int combo = 0; combo < 3; combo++) {
        const unsigned* A = (combo == 1) ? sAl : sAh;
        const unsigned* W = (combo == 2) ? sWl : sWh;
#pragma unroll 1
        for (int q = 0; q < 9; q++) {
            int dj = q / 3 - 1, dl = q % 3 - 1;
            bool jv = (unsigned)(wid + dj) < 16u;
            bool p0 = jv && ((unsigned)(g + dl) < 16u);
            bool p1 = jv && ((unsigned)(g + 8 + dl) < 16u);
            int sr0 = min(max(wid * 16 + g + dj * 16 + dl, 0), 255);
            int sr1 = min(max(wid * 16 + g + 8 + dj * 16 + dl, 0), 255);
            unsigned a[8][4];
#pragma unroll
            for (int ks = 0; ks < 8; ks++) {
                int w0 = ks * 8 + t;
                a[ks][0] = p0 ? A[sr0 * 67 + w0] : 0u;
                a[ks][1] = p1 ? A[sr1 * 67 + w0] : 0u;
                a[ks][2] = p0 ? A[sr0 * 67 + w0 + 4] : 0u;
                a[ks][3] = p1 ? A[sr1 * 67 + w0 + 4] : 0u;
            }
#pragma unroll
            for (int nt = 0; nt < 2; nt++) {
                const unsigned* brow = W + (nt * 8 + g) * 577 + q * 64;
#pragma unroll
                for (int ks = 0; ks < 8; ks++) {
                    mma16816(d[nt], a[ks], brow[ks * 8 + t], brow[ks * 8 + t + 4]);
                }
            }
        }
    }

    float lsum = 0.f;
#pragma unroll
    for (int nt = 0; nt < 2; nt++) {
#pragma unroll
        for (int r = 0; r < 4; r++) {
            int px = wid * 16 + g + ((r >= 2) ? 8 : 0);
            int co = cobase + nt * 8 + 2 * t + (r & 1);
            size_t gi = ((size_t)(b * CC + co) << 8) + px;
            float h = 0.5f * g_hs[gi] + 0.5f * d[nt][r];
            float fh = fhat[gi] + h;
            fhat[gi] = fh;
            g_frest[gi] -= h;
            float df = fh - f_in[gi];
            lsum += df * df;
        }
    }
#pragma unroll
    for (int o = 16; o > 0; o >>= 1) lsum += __shfl_xor_sync(0xFFFFFFFFu, lsum, o);
    if (lane == 0) atomicAdd(&g_loss, lsum * (0.25f / (float)FHN));
}

__global__ void final_kernel(float* __restrict__ out) {
    __shared__ float red[256];
    int tid = threadIdx.x;
    float s = 0.0f;
    for (int k = tid; k < NBCODE; k += 256) {
        float p = (float)g_counts[k] * (1.0f / (float)NTOT);
        s += p * logf(p + 1e-10f);
    }
    red[tid] = s;
    __syncthreads();
    for (int st = 128; st > 0; st >>= 1) {
        if (tid < st) red[tid] += red[tid + st];
        __syncthreads();
    }
    if (tid == 0) {
        out[FHN]     = g_loss;
        out[FHN + 1] = expf(-red[0]);
    }
}

// ------------------------------------------------------------------
extern "C" void kernel_launch(void* const* d_in, const int* in_sizes, int n_in,
                              void* d_out, int out_size) {
    const float* f     = (const float*)d_in[0];
    const float* emb   = (const float*)d_in[1];
    const float* phi_w = (const float*)d_in[2];
    const float* phi_b = (const float*)d_in[3];
    float* out = (float*)d_out;

    cudaFuncSetAttribute(coarse_kernel, cudaFuncAttributeMaxDynamicSharedMemorySize, CO_SMEM);
    cudaFuncSetAttribute(conv_mma_kernel, cudaFuncAttributeMaxDynamicSharedMemorySize, CONV_SMEM);

    prep_all<<<8256, 256>>>(f, out, emb);

    const int sns[5]     = {1, 2, 4, 8, 16};
    const int phis[5]    = {0, 1, 1, 2, 3};
    const int splits[5]  = {128, 128, 128, 64, 16};
    for (int si = 0; si < 5; si++) {
        int sn = sns[si];
        int N = BB * sn * sn;
        int fct = 16 / sn;
        int nsplit = splits[si];
        if (sn == 1) {
            pool16_kernel<<<256, 256>>>();
        } else if (sn == 2) {
            pool8_kernel<<<1024, 256>>>();
        } else if (sn == 16) {
            pool1_kernel<<<512, 256>>>();
        } else {
            pool_kernel<<<(N * CC + 255) / 256, 256>>>(sn, fct);
        }
        dim3 g((N + 255) / 256, nsplit);
        coarse_kernel<<<g, 256, CO_SMEM>>>(N, nsplit);
        refine_kernel<<<N, 256>>>(N);
        if (sn == 16) {
            gather16_kernel<<<128, 256>>>(emb);
        } else {
            upsample_kernel<<<128, 256>>>(emb, sn);
        }
        int k = phis[si];
        conv_mma_kernel<<<128, 512, CONV_SMEM>>>(phi_w + (size_t)k * CC * CC * 9,
                                                 phi_b + (size_t)k * CC, f, out);
    }
    final_kernel<<<1, 256>>>(out);
}

// round 14
// speedup vs baseline: 1.5167x; 1.0516x over previous
#include <cuda_runtime.h>
#include <cuda_bf16.h>
#include <math.h>

#define BB 16
#define CC 128
#define NBCODE 16384
#define NTOT 5456
#define FHN (BB*CC*16*16)   // 524288
#define NCHUNK 128          // 128 codes per chunk
#define CO_SMEM ((256*68 + 128*68)*4)               // 104448 bytes
#define CONV_SMEM ((2*256*67 + 2*16*577)*4)         // 211072 bytes

// ---- device scratch (no allocations allowed) ----
__device__ float g_frest[FHN];
__device__ float g_rnc[4096*CC];
__device__ float g_hs[FHN];
__device__ float g_chmin[4096*NCHUNK];
__device__ int g_idx[4096];
__device__ int g_counts[NBCODE];
__device__ float g_loss;
__device__ float g_esq[NBCODE];
__device__ int g_esqmax = 0;                  // monotone; no per-call reset needed
__device__ unsigned g_embw[NBCODE*64];        // bf16x2 words [code][64]
__device__ float g_embT[CC*NBCODE];           // transposed fp32 codebook [d][code]

// ------------------------------------------------------------------
__device__ __forceinline__ void mma16816(float* d, const unsigned* a, unsigned b0, unsigned b1) {
    asm volatile("mma.sync.aligned.m16n8k16.row.col.f32.bf16.bf16.f32 "
                 "{%0,%1,%2,%3}, {%4,%5,%6,%7}, {%8,%9}, {%0,%1,%2,%3};"
                 : "+f"(d[0]), "+f"(d[1]), "+f"(d[2]), "+f"(d[3])
                 : "r"(a[0]), "r"(a[1]), "r"(a[2]), "r"(a[3]), "r"(b0), "r"(b1));
}
__device__ __forceinline__ unsigned fkey(float f) {
    unsigned u = __float_as_uint(f);
    return (u & 0x80000000u) ? ~u : (u | 0x80000000u);
}
__device__ __forceinline__ unsigned pack2(float a, float b) {
    __nv_bfloat162 t = __floats2bfloat162_rn(a, b);
    return *(unsigned*)&t;
}

// ------------------------------------------------------------------
// Fused one-time prep: [0,2048) init, [2048,2112) esq, [2112,6208) pack,
// [6208,8256) 32x32 transpose tiles.
__global__ void prep_all(const float* __restrict__ f, float* __restrict__ fhat,
                         const float* __restrict__ emb) {
    __shared__ float t[32][33];
    int blk = blockIdx.x, tid = threadIdx.x;
    if (blk < 2048) {
        int i = blk * 256 + tid;
        fhat[i] = 0.0f;
        g_frest[i] = f[i];
        if (i < NBCODE) g_counts[i] = 0;
        if (i == 0) g_loss = 0.0f;
    } else if (blk < 2112) {
        int k = (blk - 2048) * 256 + tid;
        const float* e = emb + (size_t)k * CC;
        float s = 0.0f;
#pragma unroll 8
        for (int d = 0; d < CC; d++) s = fmaf(e[d], e[d], s);
        g_esq[k] = s;
        atomicMax(&g_esqmax, __float_as_int(s));   // s>=0: int order == float order
    } else if (blk < 6208) {
        int i = (blk - 2112) * 256 + tid;          // NBCODE*64 words
        float2 v = ((const float2*)emb)[i];
        g_embw[i] = pack2(v.x, v.y);
    } else {
        int idx = blk - 6208;                      // 2048 tiles
        int k0 = (idx & 511) * 32, d0 = (idx >> 9) * 32;
        int x = tid & 31, y0 = tid >> 5;
        for (int yy = y0; yy < 32; yy += 8)
            t[yy][x] = emb[(size_t)(k0 + yy) * CC + d0 + x];
        __syncthreads();
        for (int yy = y0; yy < 32; yy += 8)
            g_embT[(size_t)(d0 + yy) * NBCODE + k0 + x] = t[x][yy];
    }
}

// thread-per-output pooling (fct = 2,4)
__global__ void pool_kernel(int sn, int fct) {
    int i = blockIdx.x * blockDim.x + threadIdx.x;
    int N = BB * sn * sn;
    if (i >= N * CC) return;
    int n = i / CC, c = i % CC;
    int t = n % sn;
    int s = (n / sn) % sn;
    int b = n / (sn * sn);
    const float* base = g_frest + ((size_t)(b * CC + c)) * 256;
    float acc = 0.0f;
    for (int dj = 0; dj < fct; dj++)
        for (int dl = 0; dl < fct; dl++)
            acc += base[(s * fct + dj) * 16 + (t * fct + dl)];
    g_rnc[n * CC + c] = acc * (1.0f / (float)(fct * fct));
}

// warp-per-output pooling, fct=16 (sn=1)
__global__ void pool16_kernel() {
    int out = blockIdx.x * 8 + (threadIdx.x >> 5);
    int lane = threadIdx.x & 31;
    const float4* base = (const float4*)(g_frest + (size_t)out * 256);
    float4 v1 = base[lane], v2 = base[lane + 32];
    float s = v1.x + v1.y + v1.z + v1.w + v2.x + v2.y + v2.z + v2.w;
#pragma unroll
    for (int o = 16; o > 0; o >>= 1) s += __shfl_xor_sync(0xFFFFFFFFu, s, o);
    if (lane == 0) g_rnc[out] = s * (1.0f / 256.0f);
}

// warp-per-output pooling, fct=8 (sn=2)
__global__ void pool8_kernel() {
    int out = blockIdx.x * 8 + (threadIdx.x >> 5);
    int lane = threadIdx.x & 31;
    int n = out >> 7, c = out & 127;
    int t = n & 1, s = (n >> 1) & 1, b = n >> 2;
    const float* base = g_frest + ((size_t)(b * CC + c)) * 256;
    int dj = lane >> 2, dl = (lane & 3) * 2;
    const float2* p = (const float2*)(base + (s * 8 + dj) * 16 + t * 8 + dl);
    float2 v = *p;
    float sm = v.x + v.y;
#pragma unroll
    for (int o = 16; o > 0; o >>= 1) sm += __shfl_xor_sync(0xFFFFFFFFu, sm, o);
    if (lane == 0) g_rnc[out] = sm * (1.0f / 64.0f);
}

// sn=16 "pool" = identity transpose, coalesced both ways via 32x32 tiles
__global__ void pool1_kernel() {
    __shared__ float t[32][33];
    int b  = blockIdx.x >> 5;
    int ct = (blockIdx.x >> 3) & 3;
    int pt = blockIdx.x & 7;
    int x = threadIdx.x & 31, y0 = threadIdx.x >> 5;
    const float* src = g_frest + ((size_t)(b * CC + ct * 32)) * 256 + pt * 32;
    for (int yy = y0; yy < 32; yy += 8)
        t[yy][x] = src[(size_t)yy * 256 + x];
    __syncthreads();
    float* dst = g_rnc + ((size_t)(b * 256 + pt * 32)) * CC + ct * 32;
    for (int yy = y0; yy < 32; yy += 8)
        dst[(size_t)yy * CC + x] = t[x][yy];
}

// ------------------------------------------------------------------
// Coarse bf16 HMMA scoring (single pass, r2-free scores: es - 2*dot).
// Writes per-(row, 128-code chunk) minima.
__global__ __launch_bounds__(256)
void coarse_kernel(int N, int nsplit) {
    extern __shared__ unsigned sm[];
    unsigned* sA = sm;              // [256][68]
    unsigned* sB = sm + 256 * 68;   // [128][68]
    int tid = threadIdx.x, lane = tid & 31, wid = tid >> 5;
    int g = lane >> 2, t = lane & 3;
    int row0 = blockIdx.x * 256;

    const float4* rnc4 = (const float4*)g_rnc;
    for (int i = tid; i < 256 * 32; i += 256) {
        int r = i >> 5, q = i & 31;
        int rg = min(row0 + r, N - 1);
        float4 v = rnc4[(size_t)rg * 32 + q];
        sA[r * 68 + 2 * q]     = pack2(v.x, v.y);
        sA[r * 68 + 2 * q + 1] = pack2(v.z, v.w);
    }
    __syncthreads();

    unsigned a[2][8][4];
    int rl0 = wid * 32;
#pragma unroll
    for (int tile = 0; tile < 2; tile++) {
        int rb = rl0 + tile * 16;
#pragma unroll
        for (int ks = 0; ks < 8; ks++) {
            a[tile][ks][0] = sA[(rb + g    ) * 68 + ks * 8 + t];
            a[tile][ks][1] = sA[(rb + g + 8) * 68 + ks * 8 + t];
            a[tile][ks][2] = sA[(rb + g    ) * 68 + ks * 8 + t + 4];
            a[tile][ks][3] = sA[(rb + g + 8) * 68 + ks * 8 + t + 4];
        }
    }

    int rows[4];
#pragma unroll
    for (int s = 0; s < 4; s++) {
        int tile = s >> 1, half = s & 1;
        rows[s] = row0 + rl0 + tile * 16 + g + half * 8;
    }

    int cpb = NBCODE / nsplit;
    int c0s = blockIdx.y * cpb;
    const uint4* embw4 = (const uint4*)g_embw;

    for (int chunk = 0; chunk < cpb / 128; chunk++) {
        int c0 = c0s + chunk * 128;
        __syncthreads();
        for (int i = tid; i < 128 * 16; i += 256) {
            int r = i >> 4, q = i & 15;
            uint4 v = embw4[(size_t)(c0 + r) * 16 + q];
            sB[r * 68 + 4 * q]     = v.x;
            sB[r * 68 + 4 * q + 1] = v.y;
            sB[r * 68 + 4 * q + 2] = v.z;
            sB[r * 68 + 4 * q + 3] = v.w;
        }
        __syncthreads();

        float cmins[4] = {3.4e38f, 3.4e38f, 3.4e38f, 3.4e38f};
#pragma unroll 1
        for (int grp = 0; grp < 16; grp++) {
            float d0[4] = {0, 0, 0, 0}, d1[4] = {0, 0, 0, 0};
            const unsigned* brow = sB + (grp * 8 + g) * 68;
#pragma unroll
            for (int ks = 0; ks < 8; ks++) {
                unsigned b0 = brow[ks * 8 + t], b1 = brow[ks * 8 + t + 4];
                mma16816(d0, a[0][ks], b0, b1);
                mma16816(d1, a[1][ks], b0, b1);
            }
            int cc = c0 + grp * 8 + 2 * t;
            float e0 = __ldg(&g_esq[cc]), e1 = __ldg(&g_esq[cc + 1]);
            float vs[4][2] = {{d0[0], d0[1]}, {d0[2], d0[3]},
                              {d1[0], d1[1]}, {d1[2], d1[3]}};
#pragma unroll
            for (int s = 0; s < 4; s++) {
                float s0 = __fmaf_rn(-2.0f, vs[s][0], e0);
                float s1 = __fmaf_rn(-2.0f, vs[s][1], e1);
                cmins[s] = fminf(cmins[s], fminf(s0, s1));
            }
        }
        int gchunk = c0 >> 7;
#pragma unroll
        for (int s = 0; s < 4; s++) {
            float m = cmins[s];
            m = fminf(m, __shfl_xor_sync(0xFFFFFFFFu, m, 1));
            m = fminf(m, __shfl_xor_sync(0xFFFFFFFFu, m, 2));
            if (t == 0 && rows[s] < N) g_chmin[rows[s] * NCHUNK + gchunk] = m;
        }
    }
}

// fused row-min + select + exact refine + index/count. One block (512 thr)
// per row: 4 lanes-of-128, each streaming chunks s = quarter (mod 4) with
// 2-chunk ILP -> 8 chunks in flight, serial depth cnt/8. Deterministic
// ballot/popc compaction; commutative atomicMin combine.
__global__ __launch_bounds__(512)
void refine_kernel(int N) {
    __shared__ float sr[128];
    __shared__ float schm[128];
    __shared__ int sel[NCHUNK];
    __shared__ int wcnt[4];
    __shared__ int scnt;
    __shared__ unsigned long long sbest;
    __shared__ float s_r2, s_cm;
    int row = blockIdx.x;
    int tid = threadIdx.x;
    int lane = tid & 31, w = tid >> 5;
    if (tid == 0) sbest = ~0ULL;
    if (tid < 128) {
        sr[tid] = g_rnc[(size_t)row * CC + tid];
        schm[tid] = g_chmin[row * NCHUNK + tid];
    }
    __syncthreads();
    if (tid == 0) {                       // sequential r2 (bitwise == old r2_kernel)
        float s = 0.0f;
#pragma unroll 8
        for (int d = 0; d < CC; d++) s = fmaf(sr[d], sr[d], s);
        s_r2 = s;
    }
    if (w == 1) {                         // warp 1: min over 128 chunk minima
        float m = fminf(fminf(schm[lane], schm[lane + 32]),
                        fminf(schm[lane + 64], schm[lane + 96]));
#pragma unroll
        for (int o = 16; o > 0; o >>= 1) m = fminf(m, __shfl_xor_sync(0xFFFFFFFFu, m, o));
        if (lane == 0) s_cm = m;
    }
    __syncthreads();
    float r2v = s_r2;
    float emax = __int_as_float(g_esqmax);
    float thr = s_cm + 0.0320f * sqrtf(r2v * emax) + 2e-3f;

    // deterministic ordered compaction of selected chunks (tid < 128)
    bool pick = (tid < NCHUNK) && (schm[tid] <= thr);
    unsigned bal = __ballot_sync(0xFFFFFFFFu, pick);
    if (w < 4 && lane == 0) wcnt[w] = __popc(bal);
    __syncthreads();
    if (pick) {
        int base = 0;
        for (int ww = 0; ww < w; ww++) base += wcnt[ww];
        int pos = base + __popc(bal & ((1u << lane) - 1u));
        sel[pos] = tid;
    }
    if (tid == 0) scnt = wcnt[0] + wcnt[1] + wcnt[2] + wcnt[3];
    __syncthreads();

    unsigned long long best = ~0ULL;
    int quarter = tid >> 7, t = tid & 127;
    int cnt = scnt;
    int s = quarter;
    // 2 chunks per iteration per quarter (8 chunks in flight block-wide)
    for (; s + 4 < cnt; s += 8) {
        int codeA = sel[s] * 128 + t;
        int codeB = sel[s + 4] * 128 + t;
        const float* epA = g_embT + codeA;
        const float* epB = g_embT + codeB;
        float a0 = 0.f, a1 = 0.f, a2 = 0.f, a3 = 0.f;
        float b0 = 0.f, b1 = 0.f, b2 = 0.f, b3 = 0.f;
#pragma unroll 4
        for (int d = 0; d < 128; d += 4) {
            a0 = __fmaf_rn(sr[d],     epA[(size_t)(d)     * NBCODE], a0);
            b0 = __fmaf_rn(sr[d],     epB[(size_t)(d)     * NBCODE], b0);
            a1 = __fmaf_rn(sr[d + 1], epA[(size_t)(d + 1) * NBCODE], a1);
            b1 = __fmaf_rn(sr[d + 1], epB[(size_t)(d + 1) * NBCODE], b1);
            a2 = __fmaf_rn(sr[d + 2], epA[(size_t)(d + 2) * NBCODE], a2);
            b2 = __fmaf_rn(sr[d + 2], epB[(size_t)(d + 2) * NBCODE], b2);
            a3 = __fmaf_rn(sr[d + 3], epA[(size_t)(d + 3) * NBCODE], a3);
            b3 = __fmaf_rn(sr[d + 3], epB[(size_t)(d + 3) * NBCODE], b3);
        }
        float dotA = (a0 + a1) + (a2 + a3);
        float dotB = (b0 + b1) + (b2 + b3);
        float ttA = __fadd_rn(r2v, __ldg(&g_esq[codeA]));
        float scA = __fsub_rn(ttA, 2.0f * dotA);
        unsigned long long keyA = ((unsigned long long)fkey(scA) << 32) | (unsigned)codeA;
        if (keyA < best) best = keyA;
        float ttB = __fadd_rn(r2v, __ldg(&g_esq[codeB]));
        float scB = __fsub_rn(ttB, 2.0f * dotB);
        unsigned long long keyB = ((unsigned long long)fkey(scB) << 32) | (unsigned)codeB;
        if (keyB < best) best = keyB;
    }
    if (s < cnt) {
        int code = sel[s] * 128 + t;
        const float* ep = g_embT + code;
        float p0 = 0.f, p1 = 0.f, p2 = 0.f, p3 = 0.f;
#pragma unroll 8
        for (int d = 0; d < 128; d += 4) {
            p0 = __fmaf_rn(sr[d],     ep[(size_t)(d)     * NBCODE], p0);
            p1 = __fmaf_rn(sr[d + 1], ep[(size_t)(d + 1) * NBCODE], p1);
            p2 = __fmaf_rn(sr[d + 2], ep[(size_t)(d + 2) * NBCODE], p2);
            p3 = __fmaf_rn(sr[d + 3], ep[(size_t)(d + 3) * NBCODE], p3);
        }
        float dot = (p0 + p1) + (p2 + p3);
        float tt = __fadd_rn(r2v, __ldg(&g_esq[code]));   // round(r2 + e_sq)
        float sc = __fsub_rn(tt, 2.0f * dot);             // round(t - 2*dot)
        unsigned long long key = ((unsigned long long)fkey(sc) << 32) | (unsigned)code;
        if (key < best) best = key;
    }
    atomicMin(&sbest, best);
    __syncthreads();
    if (tid == 0) {
        int idx = (int)(unsigned)(sbest & 0xFFFFFFFFull);
        g_idx[row] = idx;
        atomicAdd(&g_counts[idx], 1);
    }
}

// ------------------------------------------------------------------
__device__ __forceinline__ float cubicw(float x) {
    const float a = -0.75f;
    float ax = fabsf(x);
    if (ax <= 1.0f) return ((a + 2.0f) * ax - (a + 3.0f)) * ax * ax + 1.0f;
    if (ax < 2.0f)  return a * (((ax - 5.0f) * ax + 8.0f) * ax - 4.0f);
    return 0.0f;
}

// smem-tiled bicubic upsample (sn < 16)
__global__ __launch_bounds__(256)
void upsample_kernel(const float* __restrict__ emb, int sn) {
    __shared__ float sT[32][130];
    int b   = blockIdx.x >> 3;
    int pxg = (blockIdx.x & 7) * 32;
    int tid = threadIdx.x;
    float scale = (float)sn / 16.0f;
    int c2 = (tid & 63) * 2;
    int pxl0 = tid >> 6;

#pragma unroll 2
    for (int p = 0; p < 8; p++) {
        int pxl = pxl0 * 8 + p;
        int px = pxg + pxl;
        int l = px & 15, j = px >> 4;
        float xj = (j + 0.5f) * scale - 0.5f;
        int x0j = (int)floorf(xj);
        float tj = xj - (float)x0j;
        float xl = (l + 0.5f) * scale - 0.5f;
        int x0l = (int)floorf(xl);
        float tl = xl - (float)x0l;
        float a0 = 0.f, a1 = 0.f;
#pragma unroll
        for (int kj = 0; kj < 4; kj++) {
            float wj = cubicw(tj + 1.0f - (float)kj);
            int sj = min(max(x0j - 1 + kj, 0), sn - 1);
#pragma unroll
            for (int kl = 0; kl < 4; kl++) {
                float wl = cubicw(tl + 1.0f - (float)kl);
                int sl = min(max(x0l - 1 + kl, 0), sn - 1);
                int n = (b * sn + sj) * sn + sl;
                const float2 e = *(const float2*)(emb + (size_t)g_idx[n] * CC + c2);
                float w = wj * wl;
                a0 += w * e.x;
                a1 += w * e.y;
            }
        }
        sT[pxl][c2] = a0;
        sT[pxl][c2 + 1] = a1;
    }
    __syncthreads();
    int c = tid >> 1, half = tid & 1;
    float* dst = g_hs + ((size_t)(b * CC + c)) * 256 + pxg + half * 16;
#pragma unroll
    for (int i = 0; i < 16; i += 4) {
        float4 v = make_float4(sT[half * 16 + i][c], sT[half * 16 + i + 1][c],
                               sT[half * 16 + i + 2][c], sT[half * 16 + i + 3][c]);
        *(float4*)(dst + i) = v;
    }
}

// sn == 16: identity -> coalesced gather + transpose
__global__ void gather16_kernel(const float* __restrict__ emb) {
    __shared__ float s[32 * 133];
    int tid = threadIdx.x;
    int lane = tid & 31, w = tid >> 5;
    int b  = blockIdx.x >> 3;
    int n0 = (blockIdx.x & 7) * 32;

    const float4* emb4 = (const float4*)emb;
#pragma unroll
    for (int st = 0; st < 4; st++) {
        int i = w * 4 + st;
        int idx = g_idx[b * 256 + n0 + i];
        float4 v = emb4[(size_t)idx * 32 + lane];
        s[i * 133 + lane * 4 + 0] = v.x;
        s[i * 133 + lane * 4 + 1] = v.y;
        s[i * 133 + lane * 4 + 2] = v.z;
        s[i * 133 + lane * 4 + 3] = v.w;
    }
    __syncthreads();
#pragma unroll
    for (int it = 0; it < 16; it++) {
        int c = w + it * 8;
        g_hs[(((size_t)b * 128 + c) << 8) + n0 + lane] = s[lane * 133 + c];
    }
}

// ------------------------------------------------------------------
// conv3x3 + bias as 9 shifted GEMMs on bf16 HMMA, 2-limb split
// (AhWh + AlWh + AhWl). Epilogue: phi blend, f_hat/f_rest, loss.
__global__ __launch_bounds__(512, 1)
void conv_mma_kernel(const float* __restrict__ w, const float* __restrict__ bias,
                     const float* __restrict__ f_in, float* __restrict__ fhat) {
    extern __shared__ unsigned csm[];
    unsigned* sAh = csm;                    // [256][67]
    unsigned* sAl = csm + 256 * 67;
    unsigned* sWh = csm + 2 * 256 * 67;     // [16][577]
    unsigned* sWl = sWh + 16 * 577;

    int b = blockIdx.x >> 3;
    int cobase = (blockIdx.x & 7) * 16;
    int tid = threadIdx.x;
    int lane = tid & 31, wid = tid >> 5;
    int g = lane >> 2, t = lane & 3;

    const float* hsb = g_hs + (size_t)b * CC * 256;
    for (int i = tid; i < 64 * 256; i += 512) {
        int px = i & 255, wd = i >> 8;
        float h0 = hsb[(2 * wd) * 256 + px];
        float h1 = hsb[(2 * wd + 1) * 256 + px];
        float h0h = __bfloat162float(__float2bfloat16(h0));
        float h1h = __bfloat162float(__float2bfloat16(h1));
        sAh[px * 67 + wd] = pack2(h0, h1);
        sAl[px * 67 + wd] = pack2(h0 - h0h, h1 - h1h);
    }
    __nv_bfloat16* sWhb = (__nv_bfloat16*)sWh;
    __nv_bfloat16* sWlb = (__nv_bfloat16*)sWl;
    for (int i = tid; i < 16 * 128 * 9; i += 512) {
        int q = i % 9; int ci = (i / 9) & 127; int co = i / (9 * 128);
        float wv = w[((size_t)(cobase + co) * CC + ci) * 9 + q];
        float wh = __bfloat162float(__float2bfloat16(wv));
        sWhb[(size_t)co * 1154 + q * 128 + ci] = __float2bfloat16(wv);
        sWlb[(size_t)co * 1154 + q * 128 + ci] = __float2bfloat16(wv - wh);
    }
    __syncthreads();

    float d[2][4];
#pragma unroll
    for (int nt = 0; nt < 2; nt++) {
        float bv0 = bias[cobase + nt * 8 + 2 * t];
        float bv1 = bias[cobase + nt * 8 + 2 * t + 1];
        d[nt][0] = bv0; d[nt][1] = bv1; d[nt][2] = bv0; d[nt][3] = bv1;
    }

#pragma unroll
    for (int combo = 0; combo < 3; combo++) {
        const unsigned* A = (combo == 1) ? sAl : sAh;
        const unsigned* W = (combo == 2) ? sWl : sWh;
#pragma unroll 1
        for (int q = 0; q < 9; q++) {
            int dj = q / 3 - 1, dl = q % 3 - 1;
            bool jv = (unsigned)(wid + dj) < 16u;
            bool p0 = jv && ((unsigned)(g + dl) < 16u);
            bool p1 = jv && ((unsigned)(g + 8 + dl) < 16u);
            int sr0 = min(max(wid * 16 + g + dj * 16 + dl, 0), 255);
            int sr1 = min(max(wid * 16 + g + 8 + dj * 16 + dl, 0), 255);
            unsigned a[8][4];
#pragma unroll
            for (int ks = 0; ks < 8; ks++) {
                int w0 = ks * 8 + t;
                a[ks][0] = p0 ? A[sr0 * 67 + w0] : 0u;
                a[ks][1] = p1 ? A[sr1 * 67 + w0] : 0u;
                a[ks][2] = p0 ? A[sr0 * 67 + w0 + 4] : 0u;
                a[ks][3] = p1 ? A[sr1 * 67 + w0 + 4] : 0u;
            }
#pragma unroll
            for (int nt = 0; nt < 2; nt++) {
                const unsigned* brow = W + (nt * 8 + g) * 577 + q * 64;
#pragma unroll
                for (int ks = 0; ks < 8; ks++) {
                    mma16816(d[nt], a[ks], brow[ks * 8 + t], brow[ks * 8 + t + 4]);
                }
            }
        }
    }

    float lsum = 0.f;
#pragma unroll
    for (int nt = 0; nt < 2; nt++) {
#pragma unroll
        for (int r = 0; r < 4; r++) {
            int px = wid * 16 + g + ((r >= 2) ? 8 : 0);
            int co = cobase + nt * 8 + 2 * t + (r & 1);
            size_t gi = ((size_t)(b * CC + co) << 8) + px;
            float h = 0.5f * g_hs[gi] + 0.5f * d[nt][r];
            float fh = fhat[gi] + h;
            fhat[gi] = fh;
            g_frest[gi] -= h;
            float df = fh - f_in[gi];
            lsum += df * df;
        }
    }
#pragma unroll
    for (int o = 16; o > 0; o >>= 1) lsum += __shfl_xor_sync(0xFFFFFFFFu, lsum, o);
    if (lane == 0) atomicAdd(&g_loss, lsum * (0.25f / (float)FHN));
}

__global__ void final_kernel(float* __restrict__ out) {
    __shared__ float red[256];
    int tid = threadIdx.x;
    float s = 0.0f;
    for (int k = tid; k < NBCODE; k += 256) {
        float p = (float)g_counts[k] * (1.0f / (float)NTOT);
        s += p * logf(p + 1e-10f);
    }
    red[tid] = s;
    __syncthreads();
    for (int st = 128; st > 0; st >>= 1) {
        if (tid < st) red[tid] += red[tid + st];
        __syncthreads();
    }
    if (tid == 0) {
        out[FHN]     = g_loss;
        out[FHN + 1] = expf(-red[0]);
    }
}

// ------------------------------------------------------------------
extern "C" void kernel_launch(void* const* d_in, const int* in_sizes, int n_in,
                              void* d_out, int out_size) {
    const float* f     = (const float*)d_in[0];
    const float* emb   = (const float*)d_in[1];
    const float* phi_w = (const float*)d_in[2];
    const float* phi_b = (const float*)d_in[3];
    float* out = (float*)d_out;

    cudaFuncSetAttribute(coarse_kernel, cudaFuncAttributeMaxDynamicSharedMemorySize, CO_SMEM);
    cudaFuncSetAttribute(conv_mma_kernel, cudaFuncAttributeMaxDynamicSharedMemorySize, CONV_SMEM);

    prep_all<<<8256, 256>>>(f, out, emb);

    const int sns[5]     = {1, 2, 4, 8, 16};
    const int phis[5]    = {0, 1, 1, 2, 3};
    const int splits[5]  = {128, 128, 128, 64, 16};
    for (int si = 0; si < 5; si++) {
        int sn = sns[si];
        int N = BB * sn * sn;
        int fct = 16 / sn;
        int nsplit = splits[si];
        if (sn == 1) {
            pool16_kernel<<<256, 256>>>();
        } else if (sn == 2) {
            pool8_kernel<<<1024, 256>>>();
        } else if (sn == 16) {
            pool1_kernel<<<512, 256>>>();
        } else {
            pool_kernel<<<(N * CC + 255) / 256, 256>>>(sn, fct);
        }
        dim3 g((N + 255) / 256, nsplit);
        coarse_kernel<<<g, 256, CO_SMEM>>>(N, nsplit);
        refine_kernel<<<N, 512>>>(N);
        if (sn == 16) {
            gather16_kernel<<<128, 256>>>(emb);
        } else {
            upsample_kernel<<<128, 256>>>(emb, sn);
        }
        int k = phis[si];
        conv_mma_kernel<<<128, 512, CONV_SMEM>>>(phi_w + (size_t)k * CC * CC * 9,
                                                 phi_b + (size_t)k * CC, f, out);
    }
    final_kernel<<<1, 256>>>(out);
}

// round 15
// speedup vs baseline: 1.5677x; 1.0336x over previous
#include <cuda_runtime.h>
#include <cuda_bf16.h>
#include <math.h>

#define BB 16
#define CC 128
#define NBCODE 16384
#define NTOT 5456
#define FHN (BB*CC*16*16)   // 524288
#define NCHUNK 128          // 128 codes per chunk
#define CO_SMEM ((256*68 + 128*68)*4)               // 104448 bytes
#define CONV_SMEM ((2*256*67 + 2*16*577)*4)         // 211072 bytes

// ---- device scratch (no allocations allowed) ----
__device__ float g_frest[FHN];
__device__ float g_rnc[4096*CC];
__device__ float g_hs[FHN];
__device__ float g_chmin[4096*NCHUNK];
__device__ unsigned long long g_best[4096];
__device__ int g_idx[4096];
__device__ int g_counts[NBCODE];
__device__ float g_loss;
__device__ float g_esq[NBCODE];
__device__ int g_esqmax = 0;                  // monotone; no per-call reset needed
__device__ unsigned g_embw[NBCODE*64];        // bf16x2 words [code][64]
__device__ float g_embT[CC*NBCODE];           // transposed fp32 codebook [d][code]

// ------------------------------------------------------------------
__device__ __forceinline__ void mma16816(float* d, const unsigned* a, unsigned b0, unsigned b1) {
    asm volatile("mma.sync.aligned.m16n8k16.row.col.f32.bf16.bf16.f32 "
                 "{%0,%1,%2,%3}, {%4,%5,%6,%7}, {%8,%9}, {%0,%1,%2,%3};"
                 : "+f"(d[0]), "+f"(d[1]), "+f"(d[2]), "+f"(d[3])
                 : "r"(a[0]), "r"(a[1]), "r"(a[2]), "r"(a[3]), "r"(b0), "r"(b1));
}
__device__ __forceinline__ unsigned fkey(float f) {
    unsigned u = __float_as_uint(f);
    return (u & 0x80000000u) ? ~u : (u | 0x80000000u);
}
__device__ __forceinline__ unsigned pack2(float a, float b) {
    __nv_bfloat162 t = __floats2bfloat162_rn(a, b);
    return *(unsigned*)&t;
}

// ------------------------------------------------------------------
// Fused one-time prep: [0,2048) init, [2048,2112) esq, [2112,6208) pack,
// [6208,8256) 32x32 transpose tiles.
__global__ void prep_all(const float* __restrict__ f, float* __restrict__ fhat,
                         const float* __restrict__ emb) {
    __shared__ float t[32][33];
    int blk = blockIdx.x, tid = threadIdx.x;
    if (blk < 2048) {
        int i = blk * 256 + tid;
        fhat[i] = 0.0f;
        g_frest[i] = f[i];
        if (i < NBCODE) g_counts[i] = 0;
        if (i == 0) g_loss = 0.0f;
    } else if (blk < 2112) {
        int k = (blk - 2048) * 256 + tid;
        const float* e = emb + (size_t)k * CC;
        float s = 0.0f;
#pragma unroll 8
        for (int d = 0; d < CC; d++) s = fmaf(e[d], e[d], s);
        g_esq[k] = s;
        atomicMax(&g_esqmax, __float_as_int(s));   // s>=0: int order == float order
    } else if (blk < 6208) {
        int i = (blk - 2112) * 256 + tid;          // NBCODE*64 words
        float2 v = ((const float2*)emb)[i];
        g_embw[i] = pack2(v.x, v.y);
    } else {
        int idx = blk - 6208;                      // 2048 tiles
        int k0 = (idx & 511) * 32, d0 = (idx >> 9) * 32;
        int x = tid & 31, y0 = tid >> 5;
        for (int yy = y0; yy < 32; yy += 8)
            t[yy][x] = emb[(size_t)(k0 + yy) * CC + d0 + x];
        __syncthreads();
        for (int yy = y0; yy < 32; yy += 8)
            g_embT[(size_t)(d0 + yy) * NBCODE + k0 + x] = t[x][yy];
    }
}

// thread-per-output pooling (fct = 2,4)
__global__ void pool_kernel(int sn, int fct) {
    int i = blockIdx.x * blockDim.x + threadIdx.x;
    int N = BB * sn * sn;
    if (i >= N * CC) return;
    int n = i / CC, c = i % CC;
    int t = n % sn;
    int s = (n / sn) % sn;
    int b = n / (sn * sn);
    const float* base = g_frest + ((size_t)(b * CC + c)) * 256;
    float acc = 0.0f;
    for (int dj = 0; dj < fct; dj++)
        for (int dl = 0; dl < fct; dl++)
            acc += base[(s * fct + dj) * 16 + (t * fct + dl)];
    g_rnc[n * CC + c] = acc * (1.0f / (float)(fct * fct));
}

// warp-per-output pooling, fct=16 (sn=1)
__global__ void pool16_kernel() {
    int out = blockIdx.x * 8 + (threadIdx.x >> 5);
    int lane = threadIdx.x & 31;
    const float4* base = (const float4*)(g_frest + (size_t)out * 256);
    float4 v1 = base[lane], v2 = base[lane + 32];
    float s = v1.x + v1.y + v1.z + v1.w + v2.x + v2.y + v2.z + v2.w;
#pragma unroll
    for (int o = 16; o > 0; o >>= 1) s += __shfl_xor_sync(0xFFFFFFFFu, s, o);
    if (lane == 0) g_rnc[out] = s * (1.0f / 256.0f);
}

// warp-per-output pooling, fct=8 (sn=2)
__global__ void pool8_kernel() {
    int out = blockIdx.x * 8 + (threadIdx.x >> 5);
    int lane = threadIdx.x & 31;
    int n = out >> 7, c = out & 127;
    int t = n & 1, s = (n >> 1) & 1, b = n >> 2;
    const float* base = g_frest + ((size_t)(b * CC + c)) * 256;
    int dj = lane >> 2, dl = (lane & 3) * 2;
    const float2* p = (const float2*)(base + (s * 8 + dj) * 16 + t * 8 + dl);
    float2 v = *p;
    float sm = v.x + v.y;
#pragma unroll
    for (int o = 16; o > 0; o >>= 1) sm += __shfl_xor_sync(0xFFFFFFFFu, sm, o);
    if (lane == 0) g_rnc[out] = sm * (1.0f / 64.0f);
}

// sn=16 "pool" = identity transpose, coalesced both ways via 32x32 tiles
__global__ void pool1_kernel() {
    __shared__ float t[32][33];
    int b  = blockIdx.x >> 5;
    int ct = (blockIdx.x >> 3) & 3;
    int pt = blockIdx.x & 7;
    int x = threadIdx.x & 31, y0 = threadIdx.x >> 5;
    const float* src = g_frest + ((size_t)(b * CC + ct * 32)) * 256 + pt * 32;
    for (int yy = y0; yy < 32; yy += 8)
        t[yy][x] = src[(size_t)yy * 256 + x];
    __syncthreads();
    float* dst = g_rnc + ((size_t)(b * 256 + pt * 32)) * CC + ct * 32;
    for (int yy = y0; yy < 32; yy += 8)
        dst[(size_t)yy * CC + x] = t[x][yy];
}

// ------------------------------------------------------------------
// Coarse bf16 HMMA scoring (single pass, r2-free scores: es - 2*dot).
// Writes per-(row, 128-code chunk) minima; y==0 blocks also reset g_best.
__global__ __launch_bounds__(256)
void coarse_kernel(int N, int nsplit) {
    extern __shared__ unsigned sm[];
    unsigned* sA = sm;              // [256][68]
    unsigned* sB = sm + 256 * 68;   // [128][68]
    int tid = threadIdx.x, lane = tid & 31, wid = tid >> 5;
    int g = lane >> 2, t = lane & 3;
    int row0 = blockIdx.x * 256;

    const float4* rnc4 = (const float4*)g_rnc;
    for (int i = tid; i < 256 * 32; i += 256) {
        int r = i >> 5, q = i & 31;
        int rg = min(row0 + r, N - 1);
        float4 v = rnc4[(size_t)rg * 32 + q];
        sA[r * 68 + 2 * q]     = pack2(v.x, v.y);
        sA[r * 68 + 2 * q + 1] = pack2(v.z, v.w);
    }
    __syncthreads();

    unsigned a[2][8][4];
    int rl0 = wid * 32;
#pragma unroll
    for (int tile = 0; tile < 2; tile++) {
        int rb = rl0 + tile * 16;
#pragma unroll
        for (int ks = 0; ks < 8; ks++) {
            a[tile][ks][0] = sA[(rb + g    ) * 68 + ks * 8 + t];
            a[tile][ks][1] = sA[(rb + g + 8) * 68 + ks * 8 + t];
            a[tile][ks][2] = sA[(rb + g    ) * 68 + ks * 8 + t + 4];
            a[tile][ks][3] = sA[(rb + g + 8) * 68 + ks * 8 + t + 4];
        }
    }

    int rows[4];
#pragma unroll
    for (int s = 0; s < 4; s++) {
        int tile = s >> 1, half = s & 1;
        rows[s] = row0 + rl0 + tile * 16 + g + half * 8;
        if (blockIdx.y == 0 && t == 0 && rows[s] < N) g_best[rows[s]] = ~0ULL;
    }

    int cpb = NBCODE / nsplit;
    int c0s = blockIdx.y * cpb;
    const uint4* embw4 = (const uint4*)g_embw;

    for (int chunk = 0; chunk < cpb / 128; chunk++) {
        int c0 = c0s + chunk * 128;
        __syncthreads();
        for (int i = tid; i < 128 * 16; i += 256) {
            int r = i >> 4, q = i & 15;
            uint4 v = embw4[(size_t)(c0 + r) * 16 + q];
            sB[r * 68 + 4 * q]     = v.x;
            sB[r * 68 + 4 * q + 1] = v.y;
            sB[r * 68 + 4 * q + 2] = v.z;
            sB[r * 68 + 4 * q + 3] = v.w;
        }
        __syncthreads();

        float cmins[4] = {3.4e38f, 3.4e38f, 3.4e38f, 3.4e38f};
#pragma unroll 1
        for (int grp = 0; grp < 16; grp++) {
            float d0[4] = {0, 0, 0, 0}, d1[4] = {0, 0, 0, 0};
            const unsigned* brow = sB + (grp * 8 + g) * 68;
#pragma unroll
            for (int ks = 0; ks < 8; ks++) {
                unsigned b0 = brow[ks * 8 + t], b1 = brow[ks * 8 + t + 4];
                mma16816(d0, a[0][ks], b0, b1);
                mma16816(d1, a[1][ks], b0, b1);
            }
            int cc = c0 + grp * 8 + 2 * t;
            float e0 = __ldg(&g_esq[cc]), e1 = __ldg(&g_esq[cc + 1]);
            float vs[4][2] = {{d0[0], d0[1]}, {d0[2], d0[3]},
                              {d1[0], d1[1]}, {d1[2], d1[3]}};
#pragma unroll
            for (int s = 0; s < 4; s++) {
                float s0 = __fmaf_rn(-2.0f, vs[s][0], e0);
                float s1 = __fmaf_rn(-2.0f, vs[s][1], e1);
                cmins[s] = fminf(cmins[s], fminf(s0, s1));
            }
        }
        int gchunk = c0 >> 7;
#pragma unroll
        for (int s = 0; s < 4; s++) {
            float m = cmins[s];
            m = fminf(m, __shfl_xor_sync(0xFFFFFFFFu, m, 1));
            m = fminf(m, __shfl_xor_sync(0xFFFFFFFFu, m, 2));
            if (t == 0 && rows[s] < N) g_chmin[rows[s] * NCHUNK + gchunk] = m;
        }
    }
}

// fused row-min + select + exact refine. Block = (row, y). 512 thr = 4
// lanes-of-128; global stream = blockIdx.y*4 + quarter, S = 4*gridDim.y
// streams, pairs (s, s+S) stepping 2S with dual 4-chain ILP. Selection is
// deterministic (ballot/popc, ordered by chunk id) so all y-blocks partition
// the identical list. gridDim.y==1 -> direct idx write; else atomicMin g_best.
__global__ __launch_bounds__(512)
void refine_kernel(int N) {
    __shared__ float sr[128];
    __shared__ float schm[128];
    __shared__ int sel[NCHUNK];
    __shared__ int wcnt[4];
    __shared__ int scnt;
    __shared__ unsigned long long sbest;
    __shared__ float s_r2, s_cm;
    int row = blockIdx.x;
    int tid = threadIdx.x;
    int lane = tid & 31, w = tid >> 5;
    if (tid == 0) sbest = ~0ULL;
    if (tid < 128) {
        sr[tid] = g_rnc[(size_t)row * CC + tid];
        schm[tid] = g_chmin[row * NCHUNK + tid];
    }
    __syncthreads();
    if (tid == 0) {                       // sequential r2 (bitwise == old r2_kernel)
        float s = 0.0f;
#pragma unroll 8
        for (int d = 0; d < CC; d++) s = fmaf(sr[d], sr[d], s);
        s_r2 = s;
    }
    if (w == 1) {                         // warp 1: min over 128 chunk minima
        float m = fminf(fminf(schm[lane], schm[lane + 32]),
                        fminf(schm[lane + 64], schm[lane + 96]));
#pragma unroll
        for (int o = 16; o > 0; o >>= 1) m = fminf(m, __shfl_xor_sync(0xFFFFFFFFu, m, o));
        if (lane == 0) s_cm = m;
    }
    __syncthreads();
    float r2v = s_r2;
    float emax = __int_as_float(g_esqmax);
    float thr = s_cm + 0.0320f * sqrtf(r2v * emax) + 2e-3f;

    // deterministic ordered compaction of selected chunks (tid < 128)
    bool pick = (tid < NCHUNK) && (schm[tid] <= thr);
    unsigned bal = __ballot_sync(0xFFFFFFFFu, pick);
    if (w < 4 && lane == 0) wcnt[w] = __popc(bal);
    __syncthreads();
    if (pick) {
        int base = 0;
        for (int ww = 0; ww < w; ww++) base += wcnt[ww];
        int pos = base + __popc(bal & ((1u << lane) - 1u));
        sel[pos] = tid;
    }
    if (tid == 0) scnt = wcnt[0] + wcnt[1] + wcnt[2] + wcnt[3];
    __syncthreads();

    unsigned long long best = ~0ULL;
    int quarter = tid >> 7, t = tid & 127;
    int cnt = scnt;
    int S = 4 * gridDim.y;
    int s = blockIdx.y * 4 + quarter;
    // 2 chunks per iteration per stream (8 chunks in flight per block)
    for (; s + S < cnt; s += 2 * S) {
        int codeA = sel[s] * 128 + t;
        int codeB = sel[s + S] * 128 + t;
        const float* epA = g_embT + codeA;
        const float* epB = g_embT + codeB;
        float a0 = 0.f, a1 = 0.f, a2 = 0.f, a3 = 0.f;
        float b0 = 0.f, b1 = 0.f, b2 = 0.f, b3 = 0.f;
#pragma unroll 4
        for (int d = 0; d < 128; d += 4) {
            a0 = __fmaf_rn(sr[d],     epA[(size_t)(d)     * NBCODE], a0);
            b0 = __fmaf_rn(sr[d],     epB[(size_t)(d)     * NBCODE], b0);
            a1 = __fmaf_rn(sr[d + 1], epA[(size_t)(d + 1) * NBCODE], a1);
            b1 = __fmaf_rn(sr[d + 1], epB[(size_t)(d + 1) * NBCODE], b1);
            a2 = __fmaf_rn(sr[d + 2], epA[(size_t)(d + 2) * NBCODE], a2);
            b2 = __fmaf_rn(sr[d + 2], epB[(size_t)(d + 2) * NBCODE], b2);
            a3 = __fmaf_rn(sr[d + 3], epA[(size_t)(d + 3) * NBCODE], a3);
            b3 = __fmaf_rn(sr[d + 3], epB[(size_t)(d + 3) * NBCODE], b3);
        }
        float dotA = (a0 + a1) + (a2 + a3);
        float dotB = (b0 + b1) + (b2 + b3);
        float ttA = __fadd_rn(r2v, __ldg(&g_esq[codeA]));
        float scA = __fsub_rn(ttA, 2.0f * dotA);
        unsigned long long keyA = ((unsigned long long)fkey(scA) << 32) | (unsigned)codeA;
        if (keyA < best) best = keyA;
        float ttB = __fadd_rn(r2v, __ldg(&g_esq[codeB]));
        float scB = __fsub_rn(ttB, 2.0f * dotB);
        unsigned long long keyB = ((unsigned long long)fkey(scB) << 32) | (unsigned)codeB;
        if (keyB < best) best = keyB;
    }
    if (s < cnt) {
        int code = sel[s] * 128 + t;
        const float* ep = g_embT + code;
        float p0 = 0.f, p1 = 0.f, p2 = 0.f, p3 = 0.f;
#pragma unroll 8
        for (int d = 0; d < 128; d += 4) {
            p0 = __fmaf_rn(sr[d],     ep[(size_t)(d)     * NBCODE], p0);
            p1 = __fmaf_rn(sr[d + 1], ep[(size_t)(d + 1) * NBCODE], p1);
            p2 = __fmaf_rn(sr[d + 2], ep[(size_t)(d + 2) * NBCODE], p2);
            p3 = __fmaf_rn(sr[d + 3], ep[(size_t)(d + 3) * NBCODE], p3);
        }
        float dot = (p0 + p1) + (p2 + p3);
        float tt = __fadd_rn(r2v, __ldg(&g_esq[code]));   // round(r2 + e_sq)
        float sc = __fsub_rn(tt, 2.0f * dot);             // round(t - 2*dot)
        unsigned long long key = ((unsigned long long)fkey(sc) << 32) | (unsigned)code;
        if (key < best) best = key;
    }
    atomicMin(&sbest, best);
    __syncthreads();
    if (tid == 0) {
        if (gridDim.y == 1) {
            int idx = (int)(unsigned)(sbest & 0xFFFFFFFFull);
            g_idx[row] = idx;
            atomicAdd(&g_counts[idx], 1);
        } else if (sbest != ~0ULL) {
            atomicMin(&g_best[row], sbest);
        }
    }
}

__global__ void fill_idx(int N) {
    int n = blockIdx.x * blockDim.x + threadIdx.x;
    if (n >= N) return;
    int idx = (int)(unsigned)(g_best[n] & 0xFFFFFFFFull);
    g_idx[n] = idx;
    atomicAdd(&g_counts[idx], 1);
}

// ------------------------------------------------------------------
__device__ __forceinline__ float cubicw(float x) {
    const float a = -0.75f;
    float ax = fabsf(x);
    if (ax <= 1.0f) return ((a + 2.0f) * ax - (a + 3.0f)) * ax * ax + 1.0f;
    if (ax < 2.0f)  return a * (((ax - 5.0f) * ax + 8.0f) * ax - 4.0f);
    return 0.0f;
}

// smem-tiled bicubic upsample (sn < 16)
__global__ __launch_bounds__(256)
void upsample_kernel(const float* __restrict__ emb, int sn) {
    __shared__ float sT[32][130];
    int b   = blockIdx.x >> 3;
    int pxg = (blockIdx.x & 7) * 32;
    int tid = threadIdx.x;
    float scale = (float)sn / 16.0f;
    int c2 = (tid & 63) * 2;
    int pxl0 = tid >> 6;

#pragma unroll 2
    for (int p = 0; p < 8; p++) {
        int pxl = pxl0 * 8 + p;
        int px = pxg + pxl;
        int l = px & 15, j = px >> 4;
        float xj = (j + 0.5f) * scale - 0.5f;
        int x0j = (int)floorf(xj);
        float tj = xj - (float)x0j;
        float xl = (l + 0.5f) * scale - 0.5f;
        int x0l = (int)floorf(xl);
        float tl = xl - (float)x0l;
        float a0 = 0.f, a1 = 0.f;
#pragma unroll
        for (int kj = 0; kj < 4; kj++) {
            float wj = cubicw(tj + 1.0f - (float)kj);
            int sj = min(max(x0j - 1 + kj, 0), sn - 1);
#pragma unroll
            for (int kl = 0; kl < 4; kl++) {
                float wl = cubicw(tl + 1.0f - (float)kl);
                int sl = min(max(x0l - 1 + kl, 0), sn - 1);
                int n = (b * sn + sj) * sn + sl;
                const float2 e = *(const float2*)(emb + (size_t)g_idx[n] * CC + c2);
                float w = wj * wl;
                a0 += w * e.x;
                a1 += w * e.y;
            }
        }
        sT[pxl][c2] = a0;
        sT[pxl][c2 + 1] = a1;
    }
    __syncthreads();
    int c = tid >> 1, half = tid & 1;
    float* dst = g_hs + ((size_t)(b * CC + c)) * 256 + pxg + half * 16;
#pragma unroll
    for (int i = 0; i < 16; i += 4) {
        float4 v = make_float4(sT[half * 16 + i][c], sT[half * 16 + i + 1][c],
                               sT[half * 16 + i + 2][c], sT[half * 16 + i + 3][c]);
        *(float4*)(dst + i) = v;
    }
}

// sn == 16: identity -> coalesced gather + transpose
__global__ void gather16_kernel(const float* __restrict__ emb) {
    __shared__ float s[32 * 133];
    int tid = threadIdx.x;
    int lane = tid & 31, w = tid >> 5;
    int b  = blockIdx.x >> 3;
    int n0 = (blockIdx.x & 7) * 32;

    const float4* emb4 = (const float4*)emb;
#pragma unroll
    for (int st = 0; st < 4; st++) {
        int i = w * 4 + st;
        int idx = g_idx[b * 256 + n0 + i];
        float4 v = emb4[(size_t)idx * 32 + lane];
        s[i * 133 + lane * 4 + 0] = v.x;
        s[i * 133 + lane * 4 + 1] = v.y;
        s[i * 133 + lane * 4 + 2] = v.z;
        s[i * 133 + lane * 4 + 3] = v.w;
    }
    __syncthreads();
#pragma unroll
    for (int it = 0; it < 16; it++) {
        int c = w + it * 8;
        g_hs[(((size_t)b * 128 + c) << 8) + n0 + lane] = s[lane * 133 + c];
    }
}

// ------------------------------------------------------------------
// conv3x3 + bias as 9 shifted GEMMs on bf16 HMMA, 2-limb split
// (AhWh + AlWh + AhWl). Epilogue: phi blend, f_hat/f_rest, loss.
__global__ __launch_bounds__(512, 1)
void conv_mma_kernel(const float* __restrict__ w, const float* __restrict__ bias,
                     const float* __restrict__ f_in, float* __restrict__ fhat) {
    extern __shared__ unsigned csm[];
    unsigned* sAh = csm;                    // [256][67]
    unsigned* sAl = csm + 256 * 67;
    unsigned* sWh = csm + 2 * 256 * 67;     // [16][577]
    unsigned* sWl = sWh + 16 * 577;

    int b = blockIdx.x >> 3;
    int cobase = (blockIdx.x & 7) * 16;
    int tid = threadIdx.x;
    int lane = tid & 31, wid = tid >> 5;
    int g = lane >> 2, t = lane & 3;

    const float* hsb = g_hs + (size_t)b * CC * 256;
    for (int i = tid; i < 64 * 256; i += 512) {
        int px = i & 255, wd = i >> 8;
        float h0 = hsb[(2 * wd) * 256 + px];
        float h1 = hsb[(2 * wd + 1) * 256 + px];
        float h0h = __bfloat162float(__float2bfloat16(h0));
        float h1h = __bfloat162float(__float2bfloat16(h1));
        sAh[px * 67 + wd] = pack2(h0, h1);
        sAl[px * 67 + wd] = pack2(h0 - h0h, h1 - h1h);
    }
    __nv_bfloat16* sWhb = (__nv_bfloat16*)sWh;
    __nv_bfloat16* sWlb = (__nv_bfloat16*)sWl;
    for (int i = tid; i < 16 * 128 * 9; i += 512) {
        int q = i % 9; int ci = (i / 9) & 127; int co = i / (9 * 128);
        float wv = w[((size_t)(cobase + co) * CC + ci) * 9 + q];
        float wh = __bfloat162float(__float2bfloat16(wv));
        sWhb[(size_t)co * 1154 + q * 128 + ci] = __float2bfloat16(wv);
        sWlb[(size_t)co * 1154 + q * 128 + ci] = __float2bfloat16(wv - wh);
    }
    __syncthreads();

    float d[2][4];
#pragma unroll
    for (int nt = 0; nt < 2; nt++) {
        float bv0 = bias[cobase + nt * 8 + 2 * t];
        float bv1 = bias[cobase + nt * 8 + 2 * t + 1];
        d[nt][0] = bv0; d[nt][1] = bv1; d[nt][2] = bv0; d[nt][3] = bv1;
    }

#pragma unroll
    for (int combo = 0; combo < 3; combo++) {
        const unsigned* A = (combo == 1) ? sAl : sAh;
        const unsigned* W = (combo == 2) ? sWl : sWh;
#pragma unroll 1
        for (int q = 0; q < 9; q++) {
            int dj = q / 3 - 1, dl = q % 3 - 1;
            bool jv = (unsigned)(wid + dj) < 16u;
            bool p0 = jv && ((unsigned)(g + dl) < 16u);
            bool p1 = jv && ((unsigned)(g + 8 + dl) < 16u);
            int sr0 = min(max(wid * 16 + g + dj * 16 + dl, 0), 255);
            int sr1 = min(max(wid * 16 + g + 8 + dj * 16 + dl, 0), 255);
            unsigned a[8][4];
#pragma unroll
            for (int ks = 0; ks < 8; ks++) {
                int w0 = ks * 8 + t;
                a[ks][0] = p0 ? A[sr0 * 67 + w0] : 0u;
                a[ks][1] = p1 ? A[sr1 * 67 + w0] : 0u;
                a[ks][2] = p0 ? A[sr0 * 67 + w0 + 4] : 0u;
                a[ks][3] = p1 ? A[sr1 * 67 + w0 + 4] : 0u;
            }
#pragma unroll
            for (int nt = 0; nt < 2; nt++) {
                const unsigned* brow = W + (nt * 8 + g) * 577 + q * 64;
#pragma unroll
                for (int ks = 0; ks < 8; ks++) {
                    mma16816(d[nt], a[ks], brow[ks * 8 + t], brow[ks * 8 + t + 4]);
                }
            }
        }
    }

    float lsum = 0.f;
#pragma unroll
    for (int nt = 0; nt < 2; nt++) {
#pragma unroll
        for (int r = 0; r < 4; r++) {
            int px = wid * 16 + g + ((r >= 2) ? 8 : 0);
            int co = cobase + nt * 8 + 2 * t + (r & 1);
            size_t gi = ((size_t)(b * CC + co) << 8) + px;
            float h = 0.5f * g_hs[gi] + 0.5f * d[nt][r];
            float fh = fhat[gi] + h;
            fhat[gi] = fh;
            g_frest[gi] -= h;
            float df = fh - f_in[gi];
            lsum += df * df;
        }
    }
#pragma unroll
    for (int o = 16; o > 0; o >>= 1) lsum += __shfl_xor_sync(0xFFFFFFFFu, lsum, o);
    if (lane == 0) atomicAdd(&g_loss, lsum * (0.25f / (float)FHN));
}

__global__ void final_kernel(float* __restrict__ out) {
    __shared__ float red[256];
    int tid = threadIdx.x;
    float s = 0.0f;
    for (int k = tid; k < NBCODE; k += 256) {
        float p = (float)g_counts[k] * (1.0f / (float)NTOT);
        s += p * logf(p + 1e-10f);
    }
    red[tid] = s;
    __syncthreads();
    for (int st = 128; st > 0; st >>= 1) {
        if (tid < st) red[tid] += red[tid + st];
        __syncthreads();
    }
    if (tid == 0) {
        out[FHN]     = g_loss;
        out[FHN + 1] = expf(-red[0]);
    }
}

// ------------------------------------------------------------------
extern "C" void kernel_launch(void* const* d_in, const int* in_sizes, int n_in,
                              void* d_out, int out_size) {
    const float* f     = (const float*)d_in[0];
    const float* emb   = (const float*)d_in[1];
    const float* phi_w = (const float*)d_in[2];
    const float* phi_b = (const float*)d_in[3];
    float* out = (float*)d_out;

    cudaFuncSetAttribute(coarse_kernel, cudaFuncAttributeMaxDynamicSharedMemorySize, CO_SMEM);
    cudaFuncSetAttribute(conv_mma_kernel, cudaFuncAttributeMaxDynamicSharedMemorySize, CONV_SMEM);

    prep_all<<<8256, 256>>>(f, out, emb);

    const int sns[5]     = {1, 2, 4, 8, 16};
    const int phis[5]    = {0, 1, 1, 2, 3};
    const int splits[5]  = {128, 128, 128, 64, 16};
    const int rsplit[5]  = {8, 4, 2, 1, 1};
    for (int si = 0; si < 5; si++) {
        int sn = sns[si];
        int N = BB * sn * sn;
        int fct = 16 / sn;
        int nsplit = splits[si];
        if (sn == 1) {
            pool16_kernel<<<256, 256>>>();
        } else if (sn == 2) {
            pool8_kernel<<<1024, 256>>>();
        } else if (sn == 16) {
            pool1_kernel<<<512, 256>>>();
        } else {
            pool_kernel<<<(N * CC + 255) / 256, 256>>>(sn, fct);
        }
        dim3 g((N + 255) / 256, nsplit);
        coarse_kernel<<<g, 256, CO_SMEM>>>(N, nsplit);
        dim3 rg(N, rsplit[si]);
        refine_kernel<<<rg, 512>>>(N);
        if (rsplit[si] > 1) fill_idx<<<(N + 255) / 256, 256>>>(N);
        if (sn == 16) {
            gather16_kernel<<<128, 256>>>(emb);
        } else {
            upsample_kernel<<<128, 256>>>(emb, sn);
        }
        int k = phis[si];
        conv_mma_kernel<<<128, 512, CONV_SMEM>>>(phi_w + (size_t)k * CC * CC * 9,
                                                 phi_b + (size_t)k * CC, f, out);
    }
    final_kernel<<<1, 256>>>(out);
}